// round 4
// baseline (speedup 1.0000x reference)
#include <cuda_runtime.h>
#include <cstdint>
#include <cstddef>

// ---------------- problem constants ----------------
#define NN    2048
#define KNB   48
#define NF    384
#define MIN_  1536
#define NROWS (NN*KNB)        // 98304
#define LAYERS 3

// ---------------- device scratch ----------------
__device__ float g_ET[(size_t)NROWS * NF];     // edges tf32-rounded
__device__ float g_P [(size_t)NN * 2 * NF];    // node partial sums
__device__ float g_A  [NN * NF];
__device__ float g_C  [NN * NF];
__device__ float g_S  [NN * NF];
__device__ float g_AGG[NN * NF];
__device__ float g_X  [NN * NF];
__device__ float g_Xt [NN * NF];
__device__ float g_X1 [NN * NF];
__device__ float g_X1t[NN * NF];
__device__ float g_D  [NN * NF];
__device__ float g_T  [NN * MIN_];
__device__ float g_NT [NN * NF];
// tf32-rounded weights (original [K,N] row-major layout)
__device__ float g_w0r [LAYERS * MIN_ * NF];
__device__ float g_w1r [LAYERS * NF * NF];
__device__ float g_w2r [LAYERS * NF * NF];
__device__ float g_dw0r[LAYERS * NF * MIN_];
__device__ float g_dw1r[LAYERS * MIN_ * NF];

// ---------------- helpers ----------------
__device__ __forceinline__ uint32_t f2tf(float x) {
    uint32_t r;
    asm("cvt.rna.tf32.f32 %0, %1;" : "=r"(r) : "f"(x));
    return r;
}
__device__ __forceinline__ float tf32r(float x) { return __uint_as_float(f2tf(x)); }

__device__ __forceinline__ void mma_tf32(float* c, const uint32_t* a, const uint32_t* b) {
    asm volatile(
        "mma.sync.aligned.m16n8k8.row.col.f32.tf32.tf32.f32 "
        "{%0,%1,%2,%3}, {%4,%5,%6,%7}, {%8,%9}, {%0,%1,%2,%3};\n"
        : "+f"(c[0]), "+f"(c[1]), "+f"(c[2]), "+f"(c[3])
        : "r"(a[0]), "r"(a[1]), "r"(a[2]), "r"(a[3]),
          "r"(b[0]), "r"(b[1]));
}

__device__ __forceinline__ float gelu_exact(float x) {
    return 0.5f * x * (1.0f + erff(x * 0.70710678118654752440f));
}

__device__ __forceinline__ void cp_async16(void* smem_dst, const void* gmem_src) {
    uint32_t s = (uint32_t)__cvta_generic_to_shared(smem_dst);
    asm volatile("cp.async.cg.shared.global [%0], [%1], 16;\n" :: "r"(s), "l"(gmem_src));
}
#define CP_COMMIT()  asm volatile("cp.async.commit_group;\n" ::: "memory")
#define CP_WAIT(n)   asm volatile("cp.async.wait_group %0;\n" :: "n"(n) : "memory")

// ============================================================
// Fused message kernel (per layer):
//   phase 1: H1s = round(gelu(ET[tile] @ W0b + Ab[m/48] + Cb[idx[m]]))   (smem only)
//   phase 2: H2  = gelu(H1s @ W1 + b1)  -> per-node partial sums -> P
// Tile: 64 rows x 384 cols. 256 threads = 8 warps (2 m x 4 n), warp tile 32x96.
// ============================================================
#define F_SA 36          // A-stage row stride
#define F_SB 388         // B-stage / H1s / Ps row stride
#define F_H1S_F   (64 * F_SB)                 // 24832 floats
#define F_ASTG_F  (64 * F_SA)                 // 2304
#define F_BSTG_F  (32 * F_SB)                 // 12416
#define F_STAGE_F (F_ASTG_F + F_BSTG_F)       // 14720
#define F_SMEM_BYTES ((F_H1S_F + 2 * F_STAGE_F) * 4 + 256)   // 217,344 B

__global__ __launch_bounds__(256, 1) void fused_msg_kernel(
    const float* __restrict__ ET,  const float* __restrict__ W0b,
    const float* __restrict__ W1,  const float* __restrict__ b1,
    const float* __restrict__ Ab,  const float* __restrict__ Cb,
    const int*   __restrict__ idxFlat, float* __restrict__ P)
{
    extern __shared__ float sm[];
    float* H1s = sm;                         // [64][388]
    float* St  = sm + F_H1S_F;               // 2 stages
    int*   idxs = (int*)(sm + F_H1S_F + 2 * F_STAGE_F);

    const int tid  = threadIdx.x;
    const int warp = tid >> 5;
    const int lane = tid & 31;
    const int wm   = warp >> 2;     // 0..1
    const int wn   = warp & 3;      // 0..3
    const int gid  = lane >> 2;     // 0..7
    const int tig  = lane & 3;      // 0..3
    const int m0   = blockIdx.x * 64;

    if (tid < 64) idxs[tid] = idxFlat[m0 + tid];

    float acc[2][12][4];

    // ---------------- PHASE 1 ----------------
    #pragma unroll
    for (int a = 0; a < 2; a++)
        #pragma unroll
        for (int b = 0; b < 12; b++)
            #pragma unroll
            for (int c = 0; c < 4; c++) acc[a][b][c] = 0.f;

    // produce lambda (phase 1): A tile 64x32 from ET, B tile 32x384 from W0b
    auto produce1 = [&](int kt) {
        float* As = St + (kt & 1) * F_STAGE_F;
        float* Bs = As + F_ASTG_F;
        const float* Ap = ET + (size_t)m0 * NF + kt * 32;
        #pragma unroll
        for (int i = 0; i < 2; i++) {
            int lin = tid + i * 256;
            int r = lin >> 3, c4 = (lin & 7) * 4;
            cp_async16(&As[r * F_SA + c4], Ap + (size_t)r * NF + c4);
        }
        const float* Bp = W0b + (size_t)kt * 32 * NF;
        #pragma unroll
        for (int i = 0; i < 12; i++) {
            int lin = tid + i * 256;
            int r = lin / 96, c4 = (lin % 96) * 4;
            cp_async16(&Bs[r * F_SB + c4], Bp + (size_t)r * NF + c4);
        }
        CP_COMMIT();
    };

    produce1(0);
    for (int kt = 0; kt < 12; kt++) {
        if (kt + 1 < 12) { produce1(kt + 1); CP_WAIT(1); }
        else             { CP_WAIT(0); }
        __syncthreads();

        const float* As = St + (kt & 1) * F_STAGE_F;
        const float* Bs = As + F_ASTG_F;
        #pragma unroll
        for (int kk = 0; kk < 4; kk++) {
            const int kc = kk * 8 + tig;
            uint32_t afr[2][4], bfr[12][2];
            #pragma unroll
            for (int mi = 0; mi < 2; mi++) {
                const int r = wm * 32 + mi * 16 + gid;
                afr[mi][0] = __float_as_uint(As[(r    ) * F_SA + kc    ]);
                afr[mi][1] = __float_as_uint(As[(r + 8) * F_SA + kc    ]);
                afr[mi][2] = __float_as_uint(As[(r    ) * F_SA + kc + 4]);
                afr[mi][3] = __float_as_uint(As[(r + 8) * F_SA + kc + 4]);
            }
            #pragma unroll
            for (int ni = 0; ni < 12; ni++) {
                const int c = wn * 96 + ni * 8 + gid;
                bfr[ni][0] = __float_as_uint(Bs[(kc    ) * F_SB + c]);
                bfr[ni][1] = __float_as_uint(Bs[(kc + 4) * F_SB + c]);
            }
            #pragma unroll
            for (int mi = 0; mi < 2; mi++)
                #pragma unroll
                for (int ni = 0; ni < 12; ni++)
                    mma_tf32(acc[mi][ni], afr[mi], bfr[ni]);
        }
        __syncthreads();
    }

    // phase-1 epilogue: gather-add, gelu, round -> H1s
    #pragma unroll
    for (int mi = 0; mi < 2; mi++) {
        #pragma unroll
        for (int h = 0; h < 2; h++) {
            const int r  = wm * 32 + mi * 16 + h * 8 + gid;
            const int gm = m0 + r;
            const float* aA = Ab + (size_t)(gm / KNB) * NF;
            const float* aC = Cb + (size_t)idxs[r] * NF;
            #pragma unroll
            for (int ni = 0; ni < 12; ni++) {
                const int n = wn * 96 + ni * 8 + tig * 2;
                float v0 = acc[mi][ni][h * 2 + 0] + aA[n]     + aC[n];
                float v1 = acc[mi][ni][h * 2 + 1] + aA[n + 1] + aC[n + 1];
                v0 = tf32r(gelu_exact(v0));
                v1 = tf32r(gelu_exact(v1));
                H1s[r * F_SB + n]     = v0;
                H1s[r * F_SB + n + 1] = v1;
            }
        }
    }
    __syncthreads();

    // ---------------- PHASE 2 ----------------
    #pragma unroll
    for (int a = 0; a < 2; a++)
        #pragma unroll
        for (int b = 0; b < 12; b++)
            #pragma unroll
            for (int c = 0; c < 4; c++) acc[a][b][c] = 0.f;

    auto produce2 = [&](int kt) {
        float* Bs = St + (kt & 1) * F_STAGE_F + F_ASTG_F;
        const float* Bp = W1 + (size_t)kt * 32 * NF;
        #pragma unroll
        for (int i = 0; i < 12; i++) {
            int lin = tid + i * 256;
            int r = lin / 96, c4 = (lin % 96) * 4;
            cp_async16(&Bs[r * F_SB + c4], Bp + (size_t)r * NF + c4);
        }
        CP_COMMIT();
    };

    produce2(0);
    for (int kt = 0; kt < 12; kt++) {
        if (kt + 1 < 12) { produce2(kt + 1); CP_WAIT(1); }
        else             { CP_WAIT(0); }
        __syncthreads();

        const float* Bs = St + (kt & 1) * F_STAGE_F + F_ASTG_F;
        #pragma unroll
        for (int kk = 0; kk < 4; kk++) {
            const int kc = kk * 8 + tig;
            const int kg = kt * 32 + kc;
            uint32_t afr[2][4], bfr[12][2];
            #pragma unroll
            for (int mi = 0; mi < 2; mi++) {
                const int r = wm * 32 + mi * 16 + gid;
                afr[mi][0] = __float_as_uint(H1s[(r    ) * F_SB + kg    ]);
                afr[mi][1] = __float_as_uint(H1s[(r + 8) * F_SB + kg    ]);
                afr[mi][2] = __float_as_uint(H1s[(r    ) * F_SB + kg + 4]);
                afr[mi][3] = __float_as_uint(H1s[(r + 8) * F_SB + kg + 4]);
            }
            #pragma unroll
            for (int ni = 0; ni < 12; ni++) {
                const int c = wn * 96 + ni * 8 + gid;
                bfr[ni][0] = __float_as_uint(Bs[(kc    ) * F_SB + c]);
                bfr[ni][1] = __float_as_uint(Bs[(kc + 4) * F_SB + c]);
            }
            #pragma unroll
            for (int mi = 0; mi < 2; mi++)
                #pragma unroll
                for (int ni = 0; ni < 12; ni++)
                    mma_tf32(acc[mi][ni], afr[mi], bfr[ni]);
        }
        __syncthreads();
    }

    // phase-2 epilogue: gelu(v + b1) -> Ps (overlay stage region), then node sums
    float* Ps = St;    // [64][388], reuse stage smem (K-loop finished, synced)
    #pragma unroll
    for (int mi = 0; mi < 2; mi++) {
        #pragma unroll
        for (int h = 0; h < 2; h++) {
            const int r = wm * 32 + mi * 16 + h * 8 + gid;
            #pragma unroll
            for (int ni = 0; ni < 12; ni++) {
                const int n = wn * 96 + ni * 8 + tig * 2;
                float v0 = gelu_exact(acc[mi][ni][h * 2 + 0] + b1[n]);
                float v1 = gelu_exact(acc[mi][ni][h * 2 + 1] + b1[n + 1]);
                Ps[r * F_SB + n]     = v0;
                Ps[r * F_SB + n + 1] = v1;
            }
        }
    }
    __syncthreads();

    // deterministic per-node partial sums
    const int nfirst = m0 / KNB;
    const int nlast  = (m0 + 63) / KNB;
    for (int node = nfirst; node <= nlast; node++) {
        int lo = KNB * node - m0;         if (lo < 0) lo = 0;
        int hi = KNB * node + KNB - m0;   if (hi > 64) hi = 64;
        const int  slot = (KNB * node >= m0) ? 0 : 1;
        const bool full = (KNB * node >= m0) && (KNB * node + KNB <= m0 + 64);
        for (int c = tid; c < NF; c += 256) {
            float s = 0.f;
            for (int r = lo; r < hi; r++) s += Ps[r * F_SB + c];
            P[((size_t)node * 2 + slot) * NF + c] = s;
            if (full) P[((size_t)node * 2 + 1) * NF + c] = 0.f;
        }
    }
}

// ============================================================
// Generic small TF32 GEMM (R2-proven): D = epi(A @ B), 128x128 tile.
// blockIdx.z == 1 selects the second (A2,B2,D2) problem (same M,N,K).
// flags: 1=gelu, 2=round
// ============================================================
#define BM 128
#define BN 128
#define BK 32
#define SA 36
#define SB 132
#define AS_ELEMS (2*BM*SA)
#define GEMM_SMEM_BYTES ((AS_ELEMS + 2*BK*SB) * 4)

__global__ __launch_bounds__(256) void gemm_tf32_kernel(
    const float* __restrict__ A, const float* __restrict__ B,
    float* __restrict__ D, int M, int N, int K,
    const float* __restrict__ bias, float alpha, float beta, int flags,
    const float* __restrict__ A2, const float* __restrict__ B2,
    float* __restrict__ D2)
{
    if (blockIdx.z == 1) { A = A2; B = B2; D = D2; bias = nullptr; }

    extern __shared__ float smg[];
    float* AsB = smg;
    float* BsB = smg + AS_ELEMS;

    const int tid  = threadIdx.x;
    const int m0   = blockIdx.x * BM;
    const int n0   = blockIdx.y * BN;
    const int warp = tid >> 5;
    const int lane = tid & 31;
    const int wm   = warp >> 1;
    const int wn   = warp & 1;
    const int gid  = lane >> 2;
    const int tig  = lane & 3;

    float acc[2][8][4];
    #pragma unroll
    for (int a = 0; a < 2; a++)
        #pragma unroll
        for (int b = 0; b < 8; b++)
            #pragma unroll
            for (int c = 0; c < 4; c++) acc[a][b][c] = 0.f;

    const int ar = tid >> 3;
    const int ac = (tid & 7) * 4;
    const int br = tid >> 5;
    const int bc = (tid & 31) * 4;
    const float* Abase = A + (size_t)m0 * K;
    const float* Bbase = B + n0;
    const int KT = K / BK;

    {
        #pragma unroll
        for (int i = 0; i < 4; i++)
            cp_async16(&AsB[(ar + i*32) * SA + ac], Abase + (size_t)(ar + i*32) * K + ac);
        #pragma unroll
        for (int i = 0; i < 4; i++)
            cp_async16(&BsB[(br + i*8) * SB + bc], Bbase + (size_t)(br + i*8) * N + bc);
        CP_COMMIT();
    }

    for (int kt = 0; kt < KT; kt++) {
        const int cur = kt & 1;
        if (kt + 1 < KT) {
            const int nxt = cur ^ 1;
            const float* Ap = Abase + (kt + 1) * BK;
            #pragma unroll
            for (int i = 0; i < 4; i++)
                cp_async16(&AsB[(nxt*BM + ar + i*32) * SA + ac],
                           Ap + (size_t)(ar + i*32) * K + ac);
            const float* Bp = Bbase + (size_t)(kt + 1) * BK * N;
            #pragma unroll
            for (int i = 0; i < 4; i++)
                cp_async16(&BsB[(nxt*BK + br + i*8) * SB + bc],
                           Bp + (size_t)(br + i*8) * N + bc);
            CP_COMMIT();
            CP_WAIT(1);
        } else {
            CP_WAIT(0);
        }
        __syncthreads();

        const float* Asc = AsB + cur * BM * SA;
        const float* Bsc = BsB + cur * BK * SB;
        #pragma unroll
        for (int kk = 0; kk < 4; kk++) {
            uint32_t afr[2][4], bfr[8][2];
            const int kc = kk * 8 + tig;
            #pragma unroll
            for (int mi = 0; mi < 2; mi++) {
                const int r = wm * 32 + mi * 16 + gid;
                afr[mi][0] = __float_as_uint(Asc[(r    ) * SA + kc    ]);
                afr[mi][1] = __float_as_uint(Asc[(r + 8) * SA + kc    ]);
                afr[mi][2] = __float_as_uint(Asc[(r    ) * SA + kc + 4]);
                afr[mi][3] = __float_as_uint(Asc[(r + 8) * SA + kc + 4]);
            }
            #pragma unroll
            for (int ni = 0; ni < 8; ni++) {
                const int c = wn * 64 + ni * 8 + gid;
                bfr[ni][0] = __float_as_uint(Bsc[(kc    ) * SB + c]);
                bfr[ni][1] = __float_as_uint(Bsc[(kc + 4) * SB + c]);
            }
            #pragma unroll
            for (int mi = 0; mi < 2; mi++)
                #pragma unroll
                for (int ni = 0; ni < 8; ni++)
                    mma_tf32(acc[mi][ni], afr[mi], bfr[ni]);
        }
        __syncthreads();
    }

    const int doGelu  = flags & 1;
    const int doRound = flags & 2;
    #pragma unroll
    for (int mi = 0; mi < 2; mi++) {
        #pragma unroll
        for (int h = 0; h < 2; h++) {
            const int m = m0 + wm * 32 + mi * 16 + h * 8 + gid;
            float* Drow = D + (size_t)m * N;
            #pragma unroll
            for (int ni = 0; ni < 8; ni++) {
                const int n = n0 + wn * 64 + ni * 8 + tig * 2;
                float v0 = acc[mi][ni][h * 2 + 0] * alpha;
                float v1 = acc[mi][ni][h * 2 + 1] * alpha;
                if (bias) { v0 += beta * bias[n]; v1 += beta * bias[n + 1]; }
                if (doGelu) { v0 = gelu_exact(v0); v1 = gelu_exact(v1); }
                if (doRound) { v0 = tf32r(v0); v1 = tf32r(v1); }
                *reinterpret_cast<float2*>(Drow + n) = make_float2(v0, v1);
            }
        }
    }
}

// ---------------- supporting kernels ----------------
__global__ void combine_kernel(const float* __restrict__ P, float* __restrict__ S) {
    int i = blockIdx.x;
    int n = threadIdx.x;
    float v = P[((size_t)i * 2) * NF + n] + P[((size_t)i * 2 + 1) * NF + n];
    S[(size_t)i * NF + n] = tf32r(v);
}

__global__ void ln_kernel(const float* __restrict__ a, const float* __restrict__ b,
                          const float* __restrict__ w, const float* __restrict__ bv,
                          const float* __restrict__ mask,
                          float* __restrict__ out, float* __restrict__ out2)
{
    int i = blockIdx.x;
    int n = threadIdx.x;
    float v = a[(size_t)i * NF + n] + b[(size_t)i * NF + n];

    __shared__ float s1[12], s2[12];
    float x1 = v, x2 = v * v;
    #pragma unroll
    for (int o = 16; o; o >>= 1) {
        x1 += __shfl_down_sync(0xFFFFFFFFu, x1, o);
        x2 += __shfl_down_sync(0xFFFFFFFFu, x2, o);
    }
    int wi = n >> 5, li = n & 31;
    if (li == 0) { s1[wi] = x1; s2[wi] = x2; }
    __syncthreads();
    __shared__ float mean_s, rstd_s;
    if (n == 0) {
        float t1 = 0.f, t2 = 0.f;
        #pragma unroll
        for (int j = 0; j < 12; j++) { t1 += s1[j]; t2 += s2[j]; }
        float mu  = t1 * (1.f / NF);
        float var = t2 * (1.f / NF) - mu * mu;
        mean_s = mu;
        rstd_s = rsqrtf(var + 1e-5f);
    }
    __syncthreads();
    float rr = (v - mean_s) * rstd_s * w[n] + bv[n];
    if (mask) rr *= mask[i];
    out[(size_t)i * NF + n] = rr;
    if (out2) out2[(size_t)i * NF + n] = tf32r(rr);
}

__global__ void convert_kernel(const float* __restrict__ src, float* __restrict__ dst, int n4) {
    int i = blockIdx.x * blockDim.x + threadIdx.x;
    if (i < n4) {
        float4 v = reinterpret_cast<const float4*>(src)[i];
        v.x = tf32r(v.x); v.y = tf32r(v.y); v.z = tf32r(v.z); v.w = tf32r(v.w);
        reinterpret_cast<float4*>(dst)[i] = v;
    }
}

__global__ void copy_round_kernel(const float* __restrict__ src,
                                  float* __restrict__ dst, float* __restrict__ dstR, int n) {
    int i = blockIdx.x * blockDim.x + threadIdx.x;
    if (i < n) {
        float v = src[i];
        dst[i]  = v;
        dstR[i] = tf32r(v);
    }
}

// ---------------- host orchestration ----------------
static inline void launch_gemm(const float* A, const float* B, float* D,
                               int M, int N, int K,
                               const float* bias, float alpha, float beta, int flags,
                               const float* A2 = nullptr, const float* B2 = nullptr,
                               float* D2 = nullptr)
{
    dim3 grid(M / BM, N / BN, A2 ? 2 : 1);
    gemm_tf32_kernel<<<grid, 256, GEMM_SMEM_BYTES>>>(A, B, D, M, N, K, bias,
                                                     alpha, beta, flags, A2, B2, D2);
}

static inline void launch_convert(const float* src, float* dst, size_t n) {
    int n4 = (int)(n / 4);
    convert_kernel<<<(n4 + 255) / 256, 256>>>(src, dst, n4);
}

extern "C" void kernel_launch(void* const* d_in, const int* in_sizes, int n_in,
                              void* d_out, int out_size)
{
    (void)in_sizes; (void)n_in; (void)out_size;

    const float* node  = (const float*)d_in[0];
    const float* edges = (const float*)d_in[1];
    const int*   nidx  = (const int*)  d_in[2];
    const float* mask  = (const float*)d_in[3];
    const float* w0    = (const float*)d_in[4];
    const float* b0    = (const float*)d_in[5];
    const float* w1    = (const float*)d_in[6];
    const float* b1    = (const float*)d_in[7];
    const float* w2    = (const float*)d_in[8];
    const float* b2    = (const float*)d_in[9];
    const float* ln1w  = (const float*)d_in[10];
    const float* ln1b  = (const float*)d_in[11];
    const float* dw0   = (const float*)d_in[12];
    const float* db0   = (const float*)d_in[13];
    const float* dw1   = (const float*)d_in[14];
    const float* db1   = (const float*)d_in[15];
    const float* ln2w  = (const float*)d_in[16];
    const float* ln2b  = (const float*)d_in[17];

    float *ET, *Pp, *Ab, *Cb, *Sb, *AGG, *X, *Xt, *X1, *X1t, *Dd, *T, *NT;
    float *w0r, *w1r, *w2r, *dw0r, *dw1r;
    cudaGetSymbolAddress((void**)&ET,  g_ET);
    cudaGetSymbolAddress((void**)&Pp,  g_P);
    cudaGetSymbolAddress((void**)&Ab,  g_A);
    cudaGetSymbolAddress((void**)&Cb,  g_C);
    cudaGetSymbolAddress((void**)&Sb,  g_S);
    cudaGetSymbolAddress((void**)&AGG, g_AGG);
    cudaGetSymbolAddress((void**)&X,   g_X);
    cudaGetSymbolAddress((void**)&Xt,  g_Xt);
    cudaGetSymbolAddress((void**)&X1,  g_X1);
    cudaGetSymbolAddress((void**)&X1t, g_X1t);
    cudaGetSymbolAddress((void**)&Dd,  g_D);
    cudaGetSymbolAddress((void**)&T,   g_T);
    cudaGetSymbolAddress((void**)&NT,  g_NT);
    cudaGetSymbolAddress((void**)&w0r,  g_w0r);
    cudaGetSymbolAddress((void**)&w1r,  g_w1r);
    cudaGetSymbolAddress((void**)&w2r,  g_w2r);
    cudaGetSymbolAddress((void**)&dw0r, g_dw0r);
    cudaGetSymbolAddress((void**)&dw1r, g_dw1r);

    cudaFuncSetAttribute(gemm_tf32_kernel,
                         cudaFuncAttributeMaxDynamicSharedMemorySize, GEMM_SMEM_BYTES);
    cudaFuncSetAttribute(fused_msg_kernel,
                         cudaFuncAttributeMaxDynamicSharedMemorySize, F_SMEM_BYTES);

    // ---- one-time tf32 pre-rounding ----
    launch_convert(edges, ET, (size_t)NROWS * NF);
    launch_convert(node,  NT, (size_t)NN * NF);
    launch_convert(w0,  w0r,  (size_t)LAYERS * MIN_ * NF);
    launch_convert(w1,  w1r,  (size_t)LAYERS * NF * NF);
    launch_convert(w2,  w2r,  (size_t)LAYERS * NF * NF);
    launch_convert(dw0, dw0r, (size_t)LAYERS * NF * MIN_);
    launch_convert(dw1, dw1r, (size_t)LAYERS * MIN_ * NF);
    copy_round_kernel<<<(NN * NF + 255) / 256, 256>>>(node, X, Xt, NN * NF);

    for (int i = 0; i < LAYERS; i++) {
        const float* w0L  = w0r  + (size_t)i * MIN_ * NF;   // [1536,384]
        const float* b0L  = b0   + (size_t)i * NF;
        const float* w1L  = w1r  + (size_t)i * NF * NF;
        const float* b1L  = b1   + (size_t)i * NF;
        const float* w2L  = w2r  + (size_t)i * NF * NF;
        const float* b2L  = b2   + (size_t)i * NF;
        const float* dw0L = dw0r + (size_t)i * NF * MIN_;
        const float* db0L = db0  + (size_t)i * MIN_;
        const float* dw1L = dw1r + (size_t)i * MIN_ * NF;
        const float* db1L = db1  + (size_t)i * NF;

        // (a)+(b): Ab = x@W0a + b0 ; Cb = node@W0d   (merged, gridDim.z=2)
        launch_gemm(Xt, w0L, Ab, NN, NF, NF, b0L, 1.f, 1.f, 0,
                    NT, w0L + (size_t)1152 * NF, Cb);
        // fused message path -> partial sums P
        fused_msg_kernel<<<NROWS / 64, 256, F_SMEM_BYTES>>>(
            ET, w0L + (size_t)384 * NF, w1L, b1L, Ab, Cb, nidx, Pp);
        // S = round(P0 + P1)
        combine_kernel<<<NN, NF>>>(Pp, Sb);
        // AGG = (S @ W2)/30 + (48/30) b2
        launch_gemm(Sb, w2L, AGG, NN, NF, NF, b2L, 1.f / 30.f, 48.f / 30.f, 0);
        // x1 = LN(x + AGG)
        ln_kernel<<<NN, NF>>>(X, AGG, ln1w + (size_t)i * NF, ln1b + (size_t)i * NF,
                              nullptr, X1, X1t);
        // T = round(gelu(x1 @ dense_w0 + db0))
        launch_gemm(X1t, dw0L, T, NN, MIN_, NF, db0L, 1.f, 1.f, 1 | 2);
        // D = T @ dense_w1 + db1
        launch_gemm(T, dw1L, Dd, NN, NF, MIN_, db1L, 1.f, 1.f, 0);
        // x = mask * LN(x1 + D)
        float* xout  = (i == LAYERS - 1) ? (float*)d_out : X;
        float* xout2 = (i == LAYERS - 1) ? nullptr : Xt;
        ln_kernel<<<NN, NF>>>(X1, Dd, ln2w + (size_t)i * NF, ln2b + (size_t)i * NF,
                              mask, xout, xout2);
    }
}

// round 5
// speedup vs baseline: 1.2131x; 1.2131x over previous
#include <cuda_runtime.h>
#include <cstdint>
#include <cstddef>

// ---------------- problem constants ----------------
#define NN    2048
#define KNB   48
#define NF    384
#define MIN_  1536
#define NROWS (NN*KNB)        // 98304
#define LAYERS 3

// ---------------- device scratch ----------------
__device__ float g_H1[(size_t)NROWS * NF];
__device__ float g_H2[(size_t)NROWS * NF];
__device__ float g_ET[(size_t)NROWS * NF];
__device__ float g_A  [NN * NF];
__device__ float g_C  [NN * NF];
__device__ float g_S  [NN * NF];
__device__ float g_AGG[NN * NF];
__device__ float g_X  [NN * NF];
__device__ float g_Xt [NN * NF];
__device__ float g_X1 [NN * NF];
__device__ float g_X1t[NN * NF];
__device__ float g_D  [NN * NF];
__device__ float g_T  [NN * MIN_];
__device__ float g_NT [NN * NF];
// transposed + tf32-rounded weights, [N][K] row-major (k-contiguous)
__device__ float g_w0T [LAYERS * NF * MIN_];    // [384][1536]
__device__ float g_w1T [LAYERS * NF * NF];      // [384][384]
__device__ float g_w2T [LAYERS * NF * NF];
__device__ float g_dw0T[LAYERS * MIN_ * NF];    // [1536][384]
__device__ float g_dw1T[LAYERS * NF * MIN_];    // [384][1536]

// ---------------- helpers ----------------
__device__ __forceinline__ uint32_t f2tf(float x) {
    uint32_t r;
    asm("cvt.rna.tf32.f32 %0, %1;" : "=r"(r) : "f"(x));
    return r;
}
__device__ __forceinline__ float tf32r(float x) { return __uint_as_float(f2tf(x)); }

__device__ __forceinline__ void mma_tf32(float* c, const uint32_t* a, const uint32_t* b) {
    asm volatile(
        "mma.sync.aligned.m16n8k8.row.col.f32.tf32.tf32.f32 "
        "{%0,%1,%2,%3}, {%4,%5,%6,%7}, {%8,%9}, {%0,%1,%2,%3};\n"
        : "+f"(c[0]), "+f"(c[1]), "+f"(c[2]), "+f"(c[3])
        : "r"(a[0]), "r"(a[1]), "r"(a[2]), "r"(a[3]),
          "r"(b[0]), "r"(b[1]));
}

#define LDSM_X4(r0, r1, r2, r3, addr) \
    asm volatile("ldmatrix.sync.aligned.m8n8.x4.shared.b16 {%0,%1,%2,%3}, [%4];" \
                 : "=r"(r0), "=r"(r1), "=r"(r2), "=r"(r3) : "r"(addr))

__device__ __forceinline__ float gelu_exact(float x) {
    return 0.5f * x * (1.0f + erff(x * 0.70710678118654752440f));
}

__device__ __forceinline__ void cp_async16(void* smem_dst, const void* gmem_src) {
    uint32_t s = (uint32_t)__cvta_generic_to_shared(smem_dst);
    asm volatile("cp.async.cg.shared.global [%0], [%1], 16;\n" :: "r"(s), "l"(gmem_src));
}
#define CP_COMMIT()  asm volatile("cp.async.commit_group;\n" ::: "memory")
#define CP_WAIT(n)   asm volatile("cp.async.wait_group %0;\n" :: "n"(n) : "memory")

// ============================================================
// TF32 GEMM with ldmatrix fragment loads.
//   D[M,N] = epi( A[M,K] @ Bt[N,K]^T )
// Bt is the TRANSPOSED weight, [N][K] row-major, row stride ldB.
// flags: 1=gelu, 2=round-to-tf32, 4=gather (addA[m/48] + addC[idx[m]])
// blockIdx.z==1 switches to the (A2, Bt2, D2) problem (same M,N,K,ldB; no bias).
// ============================================================
#define BM 128
#define BN 128
#define BK 32
#define SROW 36                       // floats per smem row; 16B-bank stride 9 == 1 mod 8
#define STAGE_F (128*SROW)            // 4608 floats per operand per stage
#define GEMM_SMEM_BYTES (4*STAGE_F*4) // A0,A1,B0,B1 = 73728 B

__global__ __launch_bounds__(256) void gemm_tf32_kernel(
    const float* __restrict__ A, const float* __restrict__ Bt,
    float* __restrict__ D, int M, int N, int K, int ldB,
    const float* __restrict__ bias, float alpha, float beta, int flags,
    const float* __restrict__ addA, const float* __restrict__ addC,
    const int* __restrict__ idxFlat,
    const float* __restrict__ A2, const float* __restrict__ Bt2,
    float* __restrict__ D2)
{
    if (blockIdx.z == 1) { A = A2; Bt = Bt2; D = D2; bias = nullptr; }

    extern __shared__ float smg[];     // [A stage0][A stage1][B stage0][B stage1]
    const uint32_t sbase = (uint32_t)__cvta_generic_to_shared(smg);

    const int tid  = threadIdx.x;
    const int m0   = blockIdx.x * BM;
    const int n0   = blockIdx.y * BN;
    const int warp = tid >> 5;
    const int lane = tid & 31;
    const int wm   = warp >> 1;   // 0..3
    const int wn   = warp & 1;    // 0..1
    const int gid  = lane >> 2;
    const int tig  = lane & 3;

    float acc[2][8][4];
    #pragma unroll
    for (int a = 0; a < 2; a++)
        #pragma unroll
        for (int b = 0; b < 8; b++)
            #pragma unroll
            for (int c = 0; c < 4; c++) acc[a][b][c] = 0.f;

    // cp.async coordinates: 128 rows x 32 cols per operand, 4 chunks/thread each
    const int ar = tid >> 3;            // 0..31
    const int ac = (tid & 7) * 4;       // 0,4,..,28

    // ldmatrix per-thread fragment addresses (bytes, stage 0)
    // A: matrices {rows base..+7, base+8..+15} x {k 0-3, k 4-7}
    const uint32_t aFrag = sbase +
        (uint32_t)((((tid & 15) + wm * 32) * SROW + ((tid & 16) ? 4 : 0)) * 4);
    // B: matrices {slice even rows, +4k} , {slice odd rows(+8), +4k}
    const uint32_t bFrag = sbase + (uint32_t)(2 * STAGE_F * 4) +
        (uint32_t)(((wn * 64 + (tid & 7) + ((tid & 16) ? 8 : 0)) * SROW +
                    ((tid & 8) ? 4 : 0)) * 4);

    const float* Abase = A  + (size_t)m0 * K;
    const float* Bbase = Bt + (size_t)n0 * ldB;
    const int KT = K / BK;

    auto produce = [&](int kt, int buf) {
        const float* Ap = Abase + kt * BK;
        float* As = smg + buf * STAGE_F;
        #pragma unroll
        for (int i = 0; i < 4; i++)
            cp_async16(&As[(ar + i * 32) * SROW + ac],
                       Ap + (size_t)(ar + i * 32) * K + ac);
        const float* Bp = Bbase + kt * BK;
        float* Bs = smg + (2 + buf) * STAGE_F;
        #pragma unroll
        for (int i = 0; i < 4; i++)
            cp_async16(&Bs[(ar + i * 32) * SROW + ac],
                       Bp + (size_t)(ar + i * 32) * ldB + ac);
        CP_COMMIT();
    };

    produce(0, 0);
    for (int kt = 0; kt < KT; kt++) {
        const int cur = kt & 1;
        if (kt + 1 < KT) { produce(kt + 1, cur ^ 1); CP_WAIT(1); }
        else             { CP_WAIT(0); }
        __syncthreads();

        uint32_t aA = aFrag + (uint32_t)(cur * STAGE_F * 4);
        uint32_t bA = bFrag + (uint32_t)(cur * STAGE_F * 4);
        #pragma unroll
        for (int kk = 0; kk < 4; kk++) {
            uint32_t a0[4], a1[4], b[8][2];
            LDSM_X4(a0[0], a0[1], a0[2], a0[3], aA);
            LDSM_X4(a1[0], a1[1], a1[2], a1[3], aA + 16 * SROW * 4);
            #pragma unroll
            for (int j = 0; j < 4; j++)
                LDSM_X4(b[2*j][0], b[2*j][1], b[2*j+1][0], b[2*j+1][1],
                        bA + (uint32_t)(j * 16 * SROW * 4));
            #pragma unroll
            for (int ni = 0; ni < 8; ni++) {
                mma_tf32(acc[0][ni], a0, b[ni]);
                mma_tf32(acc[1][ni], a1, b[ni]);
            }
            aA += 32;   // 8 tf32 cols = 32 bytes
            bA += 32;
        }
        __syncthreads();
    }

    // ---- epilogue ----
    const int doGelu  = flags & 1;
    const int doRound = flags & 2;
    const int doGath  = flags & 4;
    #pragma unroll
    for (int mi = 0; mi < 2; mi++) {
        #pragma unroll
        for (int h = 0; h < 2; h++) {
            const int m = m0 + wm * 32 + mi * 16 + h * 8 + gid;
            const float* aArow = nullptr;
            const float* aCrow = nullptr;
            if (doGath) {
                aArow = addA + (size_t)(m / KNB) * N;
                aCrow = addC + (size_t)idxFlat[m] * N;
            }
            float* Drow = D + (size_t)m * N;
            #pragma unroll
            for (int ni = 0; ni < 8; ni++) {
                const int n = n0 + wn * 64 + ni * 8 + tig * 2;
                float v0 = acc[mi][ni][h * 2 + 0] * alpha;
                float v1 = acc[mi][ni][h * 2 + 1] * alpha;
                if (bias) { v0 += beta * bias[n]; v1 += beta * bias[n + 1]; }
                if (doGath) {
                    v0 += aArow[n] + aCrow[n];
                    v1 += aArow[n + 1] + aCrow[n + 1];
                }
                if (doGelu) { v0 = gelu_exact(v0); v1 = gelu_exact(v1); }
                if (doRound) { v0 = tf32r(v0); v1 = tf32r(v1); }
                *reinterpret_cast<float2*>(Drow + n) = make_float2(v0, v1);
            }
        }
    }
}

// ---------------- supporting kernels ----------------
__global__ void reduce48_kernel(const float* __restrict__ H2, float* __restrict__ S) {
    int i = blockIdx.x;
    int n = threadIdx.x;
    const float* p = H2 + (size_t)i * KNB * NF + n;
    float s = 0.f;
    #pragma unroll
    for (int k = 0; k < KNB; k++) s += p[(size_t)k * NF];
    S[(size_t)i * NF + n] = tf32r(s);
}

__global__ void ln_kernel(const float* __restrict__ a, const float* __restrict__ b,
                          const float* __restrict__ w, const float* __restrict__ bv,
                          const float* __restrict__ mask,
                          float* __restrict__ out, float* __restrict__ out2)
{
    int i = blockIdx.x;
    int n = threadIdx.x;
    float v = a[(size_t)i * NF + n] + b[(size_t)i * NF + n];

    __shared__ float s1[12], s2[12];
    float x1 = v, x2 = v * v;
    #pragma unroll
    for (int o = 16; o; o >>= 1) {
        x1 += __shfl_down_sync(0xFFFFFFFFu, x1, o);
        x2 += __shfl_down_sync(0xFFFFFFFFu, x2, o);
    }
    int wi = n >> 5, li = n & 31;
    if (li == 0) { s1[wi] = x1; s2[wi] = x2; }
    __syncthreads();
    __shared__ float mean_s, rstd_s;
    if (n == 0) {
        float t1 = 0.f, t2 = 0.f;
        #pragma unroll
        for (int j = 0; j < 12; j++) { t1 += s1[j]; t2 += s2[j]; }
        float mu  = t1 * (1.f / NF);
        float var = t2 * (1.f / NF) - mu * mu;
        mean_s = mu;
        rstd_s = rsqrtf(var + 1e-5f);
    }
    __syncthreads();
    float rr = (v - mean_s) * rstd_s * w[n] + bv[n];
    if (mask) rr *= mask[i];
    out[(size_t)i * NF + n] = rr;
    if (out2) out2[(size_t)i * NF + n] = tf32r(rr);
}

__global__ void convert_kernel(const float* __restrict__ src, float* __restrict__ dst, int n4) {
    int i = blockIdx.x * blockDim.x + threadIdx.x;
    if (i < n4) {
        float4 v = reinterpret_cast<const float4*>(src)[i];
        v.x = tf32r(v.x); v.y = tf32r(v.y); v.z = tf32r(v.z); v.w = tf32r(v.w);
        reinterpret_cast<float4*>(dst)[i] = v;
    }
}

__global__ void copy_round_kernel(const float* __restrict__ src,
                                  float* __restrict__ dst, float* __restrict__ dstR, int n) {
    int i = blockIdx.x * blockDim.x + threadIdx.x;
    if (i < n) {
        float v = src[i];
        dst[i]  = v;
        dstR[i] = tf32r(v);
    }
}

// transpose + round: in [K,N] -> out [N,K]
__global__ void transpose_round_kernel(const float* __restrict__ in,
                                       float* __restrict__ out, int K, int N) {
    __shared__ float t[32][33];
    int k0 = blockIdx.x * 32, n0 = blockIdx.y * 32;
    int x = threadIdx.x, y = threadIdx.y;
    #pragma unroll
    for (int i = y; i < 32; i += 8)
        t[i][x] = in[(size_t)(k0 + i) * N + n0 + x];
    __syncthreads();
    #pragma unroll
    for (int i = y; i < 32; i += 8)
        out[(size_t)(n0 + i) * K + k0 + x] = tf32r(t[x][i]);
}

// ---------------- host orchestration ----------------
static inline void launch_gemm(const float* A, const float* Bt, float* D,
                               int M, int N, int K, int ldB,
                               const float* bias, float alpha, float beta, int flags,
                               const float* addA = nullptr, const float* addC = nullptr,
                               const int* idxFlat = nullptr,
                               const float* A2 = nullptr, const float* Bt2 = nullptr,
                               float* D2 = nullptr)
{
    dim3 grid(M / BM, N / BN, A2 ? 2 : 1);
    gemm_tf32_kernel<<<grid, 256, GEMM_SMEM_BYTES>>>(A, Bt, D, M, N, K, ldB, bias,
                                                     alpha, beta, flags,
                                                     addA, addC, idxFlat, A2, Bt2, D2);
}

static inline void launch_convert(const float* src, float* dst, size_t n) {
    int n4 = (int)(n / 4);
    convert_kernel<<<(n4 + 255) / 256, 256>>>(src, dst, n4);
}

extern "C" void kernel_launch(void* const* d_in, const int* in_sizes, int n_in,
                              void* d_out, int out_size)
{
    (void)in_sizes; (void)n_in; (void)out_size;

    const float* node  = (const float*)d_in[0];
    const float* edges = (const float*)d_in[1];
    const int*   nidx  = (const int*)  d_in[2];
    const float* mask  = (const float*)d_in[3];
    const float* w0    = (const float*)d_in[4];
    const float* b0    = (const float*)d_in[5];
    const float* w1    = (const float*)d_in[6];
    const float* b1    = (const float*)d_in[7];
    const float* w2    = (const float*)d_in[8];
    const float* b2    = (const float*)d_in[9];
    const float* ln1w  = (const float*)d_in[10];
    const float* ln1b  = (const float*)d_in[11];
    const float* dw0   = (const float*)d_in[12];
    const float* db0   = (const float*)d_in[13];
    const float* dw1   = (const float*)d_in[14];
    const float* db1   = (const float*)d_in[15];
    const float* ln2w  = (const float*)d_in[16];
    const float* ln2b  = (const float*)d_in[17];

    float *H1, *H2, *ET, *Ab, *Cb, *Sb, *AGG, *X, *Xt, *X1, *X1t, *Dd, *T, *NT;
    float *w0T, *w1T, *w2T, *dw0T, *dw1T;
    cudaGetSymbolAddress((void**)&H1,  g_H1);
    cudaGetSymbolAddress((void**)&H2,  g_H2);
    cudaGetSymbolAddress((void**)&ET,  g_ET);
    cudaGetSymbolAddress((void**)&Ab,  g_A);
    cudaGetSymbolAddress((void**)&Cb,  g_C);
    cudaGetSymbolAddress((void**)&Sb,  g_S);
    cudaGetSymbolAddress((void**)&AGG, g_AGG);
    cudaGetSymbolAddress((void**)&X,   g_X);
    cudaGetSymbolAddress((void**)&Xt,  g_Xt);
    cudaGetSymbolAddress((void**)&X1,  g_X1);
    cudaGetSymbolAddress((void**)&X1t, g_X1t);
    cudaGetSymbolAddress((void**)&Dd,  g_D);
    cudaGetSymbolAddress((void**)&T,   g_T);
    cudaGetSymbolAddress((void**)&NT,  g_NT);
    cudaGetSymbolAddress((void**)&w0T,  g_w0T);
    cudaGetSymbolAddress((void**)&w1T,  g_w1T);
    cudaGetSymbolAddress((void**)&w2T,  g_w2T);
    cudaGetSymbolAddress((void**)&dw0T, g_dw0T);
    cudaGetSymbolAddress((void**)&dw1T, g_dw1T);

    cudaFuncSetAttribute(gemm_tf32_kernel,
                         cudaFuncAttributeMaxDynamicSharedMemorySize, GEMM_SMEM_BYTES);

    // ---- one-time: round activations, transpose+round weights ----
    launch_convert(edges, ET, (size_t)NROWS * NF);
    launch_convert(node,  NT, (size_t)NN * NF);
    copy_round_kernel<<<(NN * NF + 255) / 256, 256>>>(node, X, Xt, NN * NF);

    for (int i = 0; i < LAYERS; i++) {
        transpose_round_kernel<<<dim3(MIN_/32, NF/32), dim3(32,8)>>>(
            w0 + (size_t)i*MIN_*NF, w0T + (size_t)i*NF*MIN_, MIN_, NF);
        transpose_round_kernel<<<dim3(NF/32, NF/32), dim3(32,8)>>>(
            w1 + (size_t)i*NF*NF, w1T + (size_t)i*NF*NF, NF, NF);
        transpose_round_kernel<<<dim3(NF/32, NF/32), dim3(32,8)>>>(
            w2 + (size_t)i*NF*NF, w2T + (size_t)i*NF*NF, NF, NF);
        transpose_round_kernel<<<dim3(NF/32, MIN_/32), dim3(32,8)>>>(
            dw0 + (size_t)i*NF*MIN_, dw0T + (size_t)i*MIN_*NF, NF, MIN_);
        transpose_round_kernel<<<dim3(MIN_/32, NF/32), dim3(32,8)>>>(
            dw1 + (size_t)i*MIN_*NF, dw1T + (size_t)i*NF*MIN_, MIN_, NF);
    }

    for (int i = 0; i < LAYERS; i++) {
        const float* w0L  = w0T  + (size_t)i * NF * MIN_;   // [384][1536]
        const float* b0L  = b0   + (size_t)i * NF;
        const float* w1L  = w1T  + (size_t)i * NF * NF;     // [384][384]
        const float* b1L  = b1   + (size_t)i * NF;
        const float* w2L  = w2T  + (size_t)i * NF * NF;
        const float* b2L  = b2   + (size_t)i * NF;
        const float* dw0L = dw0T + (size_t)i * MIN_ * NF;   // [1536][384]
        const float* db0L = db0  + (size_t)i * MIN_;
        const float* dw1L = dw1T + (size_t)i * NF * MIN_;   // [384][1536]
        const float* db1L = db1  + (size_t)i * NF;

        // (a)+(b) merged: Ab = x@W0a + b0 ; Cb = node@W0d
        // column slices of w0T: W0a = cols 0:384, W0d = cols 1152:1536
        launch_gemm(Xt, w0L, Ab, NN, NF, NF, MIN_, b0L, 1.f, 1.f, 0,
                    nullptr, nullptr, nullptr,
                    NT, w0L + 1152, Cb);
        // (c) H1 = round(gelu(edges @ W0b + A[m/48] + C[idx]))
        launch_gemm(ET, w0L + 384, H1, NROWS, NF, NF, MIN_,
                    nullptr, 1.f, 0.f, 1 | 2 | 4, Ab, Cb, nidx);
        // (d) H2 = round(gelu(H1 @ W1 + b1))
        launch_gemm(H1, w1L, H2, NROWS, NF, NF, NF, b1L, 1.f, 1.f, 1 | 2);
        // (e) S = round(sum_k H2)
        reduce48_kernel<<<NN, NF>>>(H2, Sb);
        // (f) AGG = (S @ W2)/30 + (48/30) b2
        launch_gemm(Sb, w2L, AGG, NN, NF, NF, NF, b2L, 1.f / 30.f, 48.f / 30.f, 0);
        // (g) x1 = LN(x + AGG)
        ln_kernel<<<NN, NF>>>(X, AGG, ln1w + (size_t)i * NF, ln1b + (size_t)i * NF,
                              nullptr, X1, X1t);
        // (h) T = round(gelu(x1 @ dense_w0 + db0))
        launch_gemm(X1t, dw0L, T, NN, MIN_, NF, NF, db0L, 1.f, 1.f, 1 | 2);
        // (i) D = T @ dense_w1 + db1
        launch_gemm(T, dw1L, Dd, NN, NF, MIN_, MIN_, db1L, 1.f, 1.f, 0);
        // (j) x = mask * LN(x1 + D)
        float* xout  = (i == LAYERS - 1) ? (float*)d_out : X;
        float* xout2 = (i == LAYERS - 1) ? nullptr : Xt;
        ln_kernel<<<NN, NF>>>(X1, Dd, ln2w + (size_t)i * NF, ln2b + (size_t)i * NF,
                              mask, xout, xout2);
    }
}

// round 7
// speedup vs baseline: 1.2741x; 1.0503x over previous
#include <cuda_runtime.h>
#include <cstdint>
#include <cstddef>

// ---------------- problem constants ----------------
#define NN    2048
#define KNB   48
#define NF    384
#define MIN_  1536
#define NROWS (NN*KNB)        // 98304
#define LAYERS 3

// ---------------- device scratch ----------------
__device__ float g_H1[(size_t)NROWS * NF];
__device__ float g_H2[(size_t)NROWS * NF];
__device__ float g_ET[(size_t)NROWS * NF];
__device__ float g_A  [NN * NF];
__device__ float g_C  [NN * NF];
__device__ float g_S  [NN * NF];
__device__ float g_AGGP[3 * NN * NF];   // split-K parts for (f)
__device__ float g_DP  [3 * NN * NF];   // split-K parts for (i)
__device__ float g_X  [NN * NF];
__device__ float g_Xt [NN * NF];
__device__ float g_X1 [NN * NF];
__device__ float g_X1t[NN * NF];
__device__ float g_T  [NN * MIN_];
__device__ float g_NT [NN * NF];
// transposed + tf32-rounded weights, [N][K] row-major (k-contiguous)
__device__ float g_w0T [LAYERS * NF * MIN_];
__device__ float g_w1T [LAYERS * NF * NF];
__device__ float g_w2T [LAYERS * NF * NF];
__device__ float g_dw0T[LAYERS * MIN_ * NF];
__device__ float g_dw1T[LAYERS * NF * MIN_];

// ---------------- helpers ----------------
__device__ __forceinline__ uint32_t f2tf(float x) {
    uint32_t r;
    asm("cvt.rna.tf32.f32 %0, %1;" : "=r"(r) : "f"(x));
    return r;
}
__device__ __forceinline__ float tf32r(float x) { return __uint_as_float(f2tf(x)); }

__device__ __forceinline__ void mma_tf32(float* c, const uint32_t* a, const uint32_t* b) {
    asm volatile(
        "mma.sync.aligned.m16n8k8.row.col.f32.tf32.tf32.f32 "
        "{%0,%1,%2,%3}, {%4,%5,%6,%7}, {%8,%9}, {%0,%1,%2,%3};\n"
        : "+f"(c[0]), "+f"(c[1]), "+f"(c[2]), "+f"(c[3])
        : "r"(a[0]), "r"(a[1]), "r"(a[2]), "r"(a[3]),
          "r"(b[0]), "r"(b[1]));
}

#define LDSM_X4(r0, r1, r2, r3, addr) \
    asm volatile("ldmatrix.sync.aligned.m8n8.x4.shared.b16 {%0,%1,%2,%3}, [%4];" \
                 : "=r"(r0), "=r"(r1), "=r"(r2), "=r"(r3) : "r"(addr))

__device__ __forceinline__ float gelu_exact(float x) {
    return 0.5f * x * (1.0f + erff(x * 0.70710678118654752440f));
}

__device__ __forceinline__ void cp_async16(void* smem_dst, const void* gmem_src) {
    uint32_t s = (uint32_t)__cvta_generic_to_shared(smem_dst);
    asm volatile("cp.async.cg.shared.global [%0], [%1], 16;\n" :: "r"(s), "l"(gmem_src));
}
#define CP_COMMIT()  asm volatile("cp.async.commit_group;\n" ::: "memory")
#define CP_WAIT(n)   asm volatile("cp.async.wait_group %0;\n" :: "n"(n) : "memory")

// ============================================================
// TF32 GEMM, ldmatrix fragments, 3-stage cp.async pipeline.
//   D[M,N] = epi( A[M,K] @ Bt[N,K]^T )
// A row stride = lda, Bt row stride = ldB. K = reduction length.
// flags: 1=gelu, 2=round-to-tf32, 4=gather (addA[m/48] + addC[idx[m]])
// splitK>1: blockIdx.z = k-part p; A += p*(K/splitK); Bt += p*(K/splitK);
//           D += p*M*N; bias only in part 0.
// splitK==1 && blockIdx.z==1: second problem (A2,Bt2,D2), no bias.
// ============================================================
#define BM 128
#define BN 128
#define BK 32
#define SROW 36
#define STAGE_F (128*SROW)               // 4608 floats
#define NSTAGE 3
#define GEMM_SMEM_BYTES (2*NSTAGE*STAGE_F*4)   // 110592 B

__global__ __launch_bounds__(256) void gemm_tf32_kernel(
    const float* __restrict__ A, const float* __restrict__ Bt,
    float* __restrict__ D, int M, int N, int K, int lda, int ldB,
    const float* __restrict__ bias, float alpha, float beta, int flags,
    const float* __restrict__ addA, const float* __restrict__ addC,
    const int* __restrict__ idxFlat,
    const float* __restrict__ A2, const float* __restrict__ Bt2,
    float* __restrict__ D2, int splitK)
{
    if (splitK > 1) {
        const int part = blockIdx.z;
        const int Kp = K / splitK;
        A  += (size_t)part * Kp;       // lda unchanged (full row stride)
        Bt += (size_t)part * Kp;       // ldB unchanged
        D  += (size_t)part * M * N;
        if (part) bias = nullptr;
        K = Kp;
    } else if (blockIdx.z == 1) {
        A = A2; Bt = Bt2; D = D2; bias = nullptr;
    }

    extern __shared__ float smg[];   // [A x NSTAGE][B x NSTAGE]
    const uint32_t sbase = (uint32_t)__cvta_generic_to_shared(smg);

    const int tid  = threadIdx.x;
    const int m0   = blockIdx.x * BM;
    const int n0   = blockIdx.y * BN;
    const int warp = tid >> 5;
    const int lane = tid & 31;
    const int wm   = warp >> 1;
    const int wn   = warp & 1;
    const int gid  = lane >> 2;
    const int tig  = lane & 3;

    float acc[2][8][4];
    #pragma unroll
    for (int a = 0; a < 2; a++)
        #pragma unroll
        for (int b = 0; b < 8; b++)
            #pragma unroll
            for (int c = 0; c < 4; c++) acc[a][b][c] = 0.f;

    const int ar = tid >> 3;
    const int ac = (tid & 7) * 4;

    const uint32_t aFrag = sbase +
        (uint32_t)((((tid & 15) + wm * 32) * SROW + ((tid & 16) ? 4 : 0)) * 4);
    const uint32_t bFrag = sbase + (uint32_t)(NSTAGE * STAGE_F * 4) +
        (uint32_t)(((wn * 64 + (tid & 7) + ((tid & 16) ? 8 : 0)) * SROW +
                    ((tid & 8) ? 4 : 0)) * 4);

    const float* Abase = A  + (size_t)m0 * lda;
    const float* Bbase = Bt + (size_t)n0 * ldB;
    const int KT = K / BK;

    auto produce = [&](int kt, int buf) {
        const float* Ap = Abase + kt * BK;
        float* As = smg + buf * STAGE_F;
        #pragma unroll
        for (int i = 0; i < 4; i++)
            cp_async16(&As[(ar + i * 32) * SROW + ac],
                       Ap + (size_t)(ar + i * 32) * lda + ac);
        const float* Bp = Bbase + kt * BK;
        float* Bs = smg + (NSTAGE + buf) * STAGE_F;
        #pragma unroll
        for (int i = 0; i < 4; i++)
            cp_async16(&Bs[(ar + i * 32) * SROW + ac],
                       Bp + (size_t)(ar + i * 32) * ldB + ac);
        CP_COMMIT();
    };

    produce(0, 0);
    produce(1, 1);
    for (int kt = 0; kt < KT; kt++) {
        const int cur = kt % NSTAGE;
        if (kt + 2 < KT)      { produce(kt + 2, (kt + 2) % NSTAGE); CP_WAIT(2); }
        else if (kt + 1 < KT) { CP_WAIT(1); }
        else                  { CP_WAIT(0); }
        __syncthreads();

        uint32_t aA = aFrag + (uint32_t)(cur * STAGE_F * 4);
        uint32_t bA = bFrag + (uint32_t)(cur * STAGE_F * 4);
        #pragma unroll
        for (int kk = 0; kk < 4; kk++) {
            uint32_t a0[4], a1[4], b[8][2];
            LDSM_X4(a0[0], a0[1], a0[2], a0[3], aA);
            LDSM_X4(a1[0], a1[1], a1[2], a1[3], aA + 16 * SROW * 4);
            #pragma unroll
            for (int j = 0; j < 4; j++)
                LDSM_X4(b[2*j][0], b[2*j][1], b[2*j+1][0], b[2*j+1][1],
                        bA + (uint32_t)(j * 16 * SROW * 4));
            #pragma unroll
            for (int ni = 0; ni < 8; ni++) {
                mma_tf32(acc[0][ni], a0, b[ni]);
                mma_tf32(acc[1][ni], a1, b[ni]);
            }
            aA += 32;
            bA += 32;
        }
        __syncthreads();
    }

    // ---- epilogue ----
    const int doGelu  = flags & 1;
    const int doRound = flags & 2;
    const int doGath  = flags & 4;
    #pragma unroll
    for (int mi = 0; mi < 2; mi++) {
        #pragma unroll
        for (int h = 0; h < 2; h++) {
            const int m = m0 + wm * 32 + mi * 16 + h * 8 + gid;
            const float* aArow = nullptr;
            const float* aCrow = nullptr;
            if (doGath) {
                aArow = addA + (size_t)(m / KNB) * N;
                aCrow = addC + (size_t)idxFlat[m] * N;
            }
            float* Drow = D + (size_t)m * N;
            #pragma unroll
            for (int ni = 0; ni < 8; ni++) {
                const int n = n0 + wn * 64 + ni * 8 + tig * 2;
                float v0 = acc[mi][ni][h * 2 + 0] * alpha;
                float v1 = acc[mi][ni][h * 2 + 1] * alpha;
                if (bias) { v0 += beta * bias[n]; v1 += beta * bias[n + 1]; }
                if (doGath) {
                    v0 += aArow[n] + aCrow[n];
                    v1 += aArow[n + 1] + aCrow[n + 1];
                }
                if (doGelu) { v0 = gelu_exact(v0); v1 = gelu_exact(v1); }
                if (doRound) { v0 = tf32r(v0); v1 = tf32r(v1); }
                *reinterpret_cast<float2*>(Drow + n) = make_float2(v0, v1);
            }
        }
    }
}

// ---------------- supporting kernels ----------------
__global__ void reduce48_kernel(const float* __restrict__ H2, float* __restrict__ S) {
    int i = blockIdx.x;
    int n = threadIdx.x;
    const float* p = H2 + (size_t)i * KNB * NF + n;
    float s = 0.f;
    #pragma unroll
    for (int k = 0; k < KNB; k++) s += p[(size_t)k * NF];
    S[(size_t)i * NF + n] = tf32r(s);
}

// layernorm of (a + p0 [+ p1] [+ p2]); out2 = round(out) optional; mask optional
__global__ void ln_kernel(const float* __restrict__ a,
                          const float* __restrict__ p0,
                          const float* __restrict__ p1,
                          const float* __restrict__ p2,
                          const float* __restrict__ w, const float* __restrict__ bv,
                          const float* __restrict__ mask,
                          float* __restrict__ out, float* __restrict__ out2)
{
    int i = blockIdx.x;
    int n = threadIdx.x;
    size_t o = (size_t)i * NF + n;
    float v = a[o] + p0[o];
    if (p1) v += p1[o];
    if (p2) v += p2[o];

    __shared__ float s1[12], s2[12];
    float x1 = v, x2 = v * v;
    #pragma unroll
    for (int off = 16; off; off >>= 1) {
        x1 += __shfl_down_sync(0xFFFFFFFFu, x1, off);
        x2 += __shfl_down_sync(0xFFFFFFFFu, x2, off);
    }
    int wi = n >> 5, li = n & 31;
    if (li == 0) { s1[wi] = x1; s2[wi] = x2; }
    __syncthreads();
    __shared__ float mean_s, rstd_s;
    if (n == 0) {
        float t1 = 0.f, t2 = 0.f;
        #pragma unroll
        for (int j = 0; j < 12; j++) { t1 += s1[j]; t2 += s2[j]; }
        float mu  = t1 * (1.f / NF);
        float var = t2 * (1.f / NF) - mu * mu;
        mean_s = mu;
        rstd_s = rsqrtf(var + 1e-5f);
    }
    __syncthreads();
    float rr = (v - mean_s) * rstd_s * w[n] + bv[n];
    if (mask) rr *= mask[i];
    out[o] = rr;
    if (out2) out2[o] = tf32r(rr);
}

__global__ void convert_kernel(const float* __restrict__ src, float* __restrict__ dst, int n4) {
    int i = blockIdx.x * blockDim.x + threadIdx.x;
    if (i < n4) {
        float4 v = reinterpret_cast<const float4*>(src)[i];
        v.x = tf32r(v.x); v.y = tf32r(v.y); v.z = tf32r(v.z); v.w = tf32r(v.w);
        reinterpret_cast<float4*>(dst)[i] = v;
    }
}

// node -> X (copy), Xt (round), NT (round)
__global__ void copy_round3_kernel(const float* __restrict__ src,
                                   float* __restrict__ dst,
                                   float* __restrict__ dstR,
                                   float* __restrict__ dstR2, int n) {
    int i = blockIdx.x * blockDim.x + threadIdx.x;
    if (i < n) {
        float v = src[i];
        float r = tf32r(v);
        dst[i]   = v;
        dstR[i]  = r;
        dstR2[i] = r;
    }
}

// all weight transposes (+round) in one launch; z = type*3 + layer
__global__ void transpose_all_kernel(
    const float* __restrict__ w0,  const float* __restrict__ w1,
    const float* __restrict__ w2,  const float* __restrict__ dw0,
    const float* __restrict__ dw1,
    float* __restrict__ w0T,  float* __restrict__ w1T,
    float* __restrict__ w2T,  float* __restrict__ dw0T,
    float* __restrict__ dw1T)
{
    const int z = blockIdx.z;
    const int type = z / 3, layer = z % 3;
    const float* in; float* out; int K, N;
    switch (type) {
        case 0: in = w0  + (size_t)layer*MIN_*NF; out = w0T  + (size_t)layer*NF*MIN_; K = MIN_; N = NF;   break;
        case 1: in = w1  + (size_t)layer*NF*NF;   out = w1T  + (size_t)layer*NF*NF;   K = NF;   N = NF;   break;
        case 2: in = w2  + (size_t)layer*NF*NF;   out = w2T  + (size_t)layer*NF*NF;   K = NF;   N = NF;   break;
        case 3: in = dw0 + (size_t)layer*NF*MIN_; out = dw0T + (size_t)layer*MIN_*NF; K = NF;   N = MIN_; break;
        default:in = dw1 + (size_t)layer*MIN_*NF; out = dw1T + (size_t)layer*NF*MIN_; K = MIN_; N = NF;   break;
    }
    const int k0 = blockIdx.x * 32, n0 = blockIdx.y * 32;
    if (k0 >= K || n0 >= N) return;

    __shared__ float t[32][33];
    const int x = threadIdx.x, y = threadIdx.y;
    #pragma unroll
    for (int i = y; i < 32; i += 8)
        t[i][x] = in[(size_t)(k0 + i) * N + n0 + x];
    __syncthreads();
    #pragma unroll
    for (int i = y; i < 32; i += 8)
        out[(size_t)(n0 + i) * K + k0 + x] = tf32r(t[x][i]);
}

// ---------------- host orchestration ----------------
static inline void launch_gemm(const float* A, const float* Bt, float* D,
                               int M, int N, int K, int lda, int ldB,
                               const float* bias, float alpha, float beta, int flags,
                               const float* addA = nullptr, const float* addC = nullptr,
                               const int* idxFlat = nullptr,
                               const float* A2 = nullptr, const float* Bt2 = nullptr,
                               float* D2 = nullptr, int splitK = 1)
{
    dim3 grid(M / BM, N / BN, splitK > 1 ? splitK : (A2 ? 2 : 1));
    gemm_tf32_kernel<<<grid, 256, GEMM_SMEM_BYTES>>>(A, Bt, D, M, N, K, lda, ldB,
                                                     bias, alpha, beta, flags,
                                                     addA, addC, idxFlat,
                                                     A2, Bt2, D2, splitK);
}

extern "C" void kernel_launch(void* const* d_in, const int* in_sizes, int n_in,
                              void* d_out, int out_size)
{
    (void)in_sizes; (void)n_in; (void)out_size;

    const float* node  = (const float*)d_in[0];
    const float* edges = (const float*)d_in[1];
    const int*   nidx  = (const int*)  d_in[2];
    const float* mask  = (const float*)d_in[3];
    const float* w0    = (const float*)d_in[4];
    const float* b0    = (const float*)d_in[5];
    const float* w1    = (const float*)d_in[6];
    const float* b1    = (const float*)d_in[7];
    const float* w2    = (const float*)d_in[8];
    const float* b2    = (const float*)d_in[9];
    const float* ln1w  = (const float*)d_in[10];
    const float* ln1b  = (const float*)d_in[11];
    const float* dw0   = (const float*)d_in[12];
    const float* db0   = (const float*)d_in[13];
    const float* dw1   = (const float*)d_in[14];
    const float* db1   = (const float*)d_in[15];
    const float* ln2w  = (const float*)d_in[16];
    const float* ln2b  = (const float*)d_in[17];

    float *H1, *H2, *ET, *Ab, *Cb, *Sb, *AGGP, *DP, *X, *Xt, *X1, *X1t, *T, *NT;
    float *w0T, *w1T, *w2T, *dw0T, *dw1T;
    cudaGetSymbolAddress((void**)&H1,   g_H1);
    cudaGetSymbolAddress((void**)&H2,   g_H2);
    cudaGetSymbolAddress((void**)&ET,   g_ET);
    cudaGetSymbolAddress((void**)&Ab,   g_A);
    cudaGetSymbolAddress((void**)&Cb,   g_C);
    cudaGetSymbolAddress((void**)&Sb,   g_S);
    cudaGetSymbolAddress((void**)&AGGP, g_AGGP);
    cudaGetSymbolAddress((void**)&DP,   g_DP);
    cudaGetSymbolAddress((void**)&X,    g_X);
    cudaGetSymbolAddress((void**)&Xt,   g_Xt);
    cudaGetSymbolAddress((void**)&X1,   g_X1);
    cudaGetSymbolAddress((void**)&X1t,  g_X1t);
    cudaGetSymbolAddress((void**)&T,    g_T);
    cudaGetSymbolAddress((void**)&NT,   g_NT);
    cudaGetSymbolAddress((void**)&w0T,  g_w0T);
    cudaGetSymbolAddress((void**)&w1T,  g_w1T);
    cudaGetSymbolAddress((void**)&w2T,  g_w2T);
    cudaGetSymbolAddress((void**)&dw0T, g_dw0T);
    cudaGetSymbolAddress((void**)&dw1T, g_dw1T);

    cudaFuncSetAttribute(gemm_tf32_kernel,
                         cudaFuncAttributeMaxDynamicSharedMemorySize, GEMM_SMEM_BYTES);

    // ---- preamble (3 launches so launch #5 is a big GEMM for ncu) ----
    {
        int n4 = (int)((size_t)NROWS * NF / 4);
        convert_kernel<<<(n4 + 255) / 256, 256>>>(edges, ET, n4);            // launch 0
    }
    copy_round3_kernel<<<(NN * NF + 255) / 256, 256>>>(node, X, Xt, NT, NN * NF); // 1
    transpose_all_kernel<<<dim3(48, 48, 15), dim3(32, 8)>>>(
        w0, w1, w2, dw0, dw1, w0T, w1T, w2T, dw0T, dw1T);                    // 2

    for (int i = 0; i < LAYERS; i++) {
        const float* w0L  = w0T  + (size_t)i * NF * MIN_;
        const float* b0L  = b0   + (size_t)i * NF;
        const float* w1L  = w1T  + (size_t)i * NF * NF;
        const float* b1L  = b1   + (size_t)i * NF;
        const float* w2L  = w2T  + (size_t)i * NF * NF;
        const float* b2L  = b2   + (size_t)i * NF;
        const float* dw0L = dw0T + (size_t)i * MIN_ * NF;
        const float* db0L = db0  + (size_t)i * MIN_;
        const float* dw1L = dw1T + (size_t)i * NF * MIN_;
        const float* db1L = db1  + (size_t)i * NF;

        // (a)+(b) merged: Ab = x@W0a + b0 ; Cb = node@W0d        (launch 3)
        launch_gemm(Xt, w0L, Ab, NN, NF, NF, NF, MIN_, b0L, 1.f, 1.f, 0,
                    nullptr, nullptr, nullptr,
                    NT, w0L + 1152, Cb);
        // (c) H1 = round(gelu(edges @ W0b + A[m/48] + C[idx]))    (launch 4)
        launch_gemm(ET, w0L + 384, H1, NROWS, NF, NF, NF, MIN_,
                    nullptr, 1.f, 0.f, 1 | 2 | 4, Ab, Cb, nidx);
        // (d) H2 = round(gelu(H1 @ W1 + b1))                      (launch 5 <- ncu)
        launch_gemm(H1, w1L, H2, NROWS, NF, NF, NF, NF, b1L, 1.f, 1.f, 1 | 2);
        // (e) S = round(sum_k H2)
        reduce48_kernel<<<NN, NF>>>(H2, Sb);
        // (f) AGG parts = (S @ W2)/30 (+ (48/30) b2 in part 0), split-K=3
        launch_gemm(Sb, w2L, AGGP, NN, NF, NF, NF, NF, b2L, 1.f / 30.f, 48.f / 30.f, 0,
                    nullptr, nullptr, nullptr, nullptr, nullptr, nullptr, 3);
        // (g) x1 = LN(x + sum AGG parts)
        ln_kernel<<<NN, NF>>>(X, AGGP, AGGP + (size_t)NN * NF, AGGP + (size_t)2 * NN * NF,
                              ln1w + (size_t)i * NF, ln1b + (size_t)i * NF,
                              nullptr, X1, X1t);
        // (h) T = round(gelu(x1 @ dense_w0 + db0))
        launch_gemm(X1t, dw0L, T, NN, MIN_, NF, NF, NF, db0L, 1.f, 1.f, 1 | 2);
        // (i) D parts = T @ dense_w1 (+ db1 in part 0), split-K=3
        launch_gemm(T, dw1L, DP, NN, NF, MIN_, MIN_, MIN_, db1L, 1.f, 1.f, 0,
                    nullptr, nullptr, nullptr, nullptr, nullptr, nullptr, 3);
        // (j) x = mask * LN(x1 + sum D parts)
        float* xout  = (i == LAYERS - 1) ? (float*)d_out : X;
        float* xout2 = (i == LAYERS - 1) ? nullptr : Xt;
        ln_kernel<<<NN, NF>>>(X1, DP, DP + (size_t)NN * NF, DP + (size_t)2 * NN * NF,
                              ln2w + (size_t)i * NF, ln2b + (size_t)i * NF,
                              mask, xout, xout2);
    }
}

// round 9
// speedup vs baseline: 1.5605x; 1.2248x over previous
#include <cuda_runtime.h>
#include <cuda_fp16.h>
#include <cstdint>
#include <cstddef>

// ---------------- problem constants ----------------
#define NN    2048
#define KNB   48
#define NF    384
#define MIN_  1536
#define NROWS (NN*KNB)        // 98304
#define LAYERS 3

// ---------------- device scratch ----------------
__device__ __half g_ET[(size_t)NROWS * NF];
__device__ __half g_H1[(size_t)NROWS * NF];
__device__ __half g_H2[(size_t)NROWS * NF];
__device__ __half g_T [NN * MIN_];
__device__ __half g_Xt [NN * NF];
__device__ __half g_NT [NN * NF];
__device__ __half g_X1t[NN * NF];
__device__ __half g_Sb [NN * NF];
__device__ float  g_A  [NN * NF];
__device__ float  g_C  [NN * NF];
__device__ float  g_AGGP[3 * NN * NF];
__device__ float  g_DP  [3 * NN * NF];
__device__ float  g_X  [NN * NF];
__device__ float  g_X1 [NN * NF];
// transposed fp16 weights, [N][K] row-major (k-contiguous)
__device__ __half g_w0T [LAYERS * NF * MIN_];
__device__ __half g_w1T [LAYERS * NF * NF];
__device__ __half g_w2T [LAYERS * NF * NF];
__device__ __half g_dw0T[LAYERS * MIN_ * NF];
__device__ __half g_dw1T[LAYERS * NF * MIN_];

// ---------------- helpers ----------------
__device__ __forceinline__ float gelu_exact(float x) {
    return 0.5f * x * (1.0f + erff(x * 0.70710678118654752440f));
}

__device__ __forceinline__ void mma_f16(float* c, const uint32_t* a, const uint32_t* b) {
    asm volatile(
        "mma.sync.aligned.m16n8k16.row.col.f32.f16.f16.f32 "
        "{%0,%1,%2,%3}, {%4,%5,%6,%7}, {%8,%9}, {%0,%1,%2,%3};\n"
        : "+f"(c[0]), "+f"(c[1]), "+f"(c[2]), "+f"(c[3])
        : "r"(a[0]), "r"(a[1]), "r"(a[2]), "r"(a[3]),
          "r"(b[0]), "r"(b[1]));
}

#define LDSM_X4(r0, r1, r2, r3, addr) \
    asm volatile("ldmatrix.sync.aligned.m8n8.x4.shared.b16 {%0,%1,%2,%3}, [%4];" \
                 : "=r"(r0), "=r"(r1), "=r"(r2), "=r"(r3) : "r"(addr))

__device__ __forceinline__ void cp_async16(void* smem_dst, const void* gmem_src) {
    uint32_t s = (uint32_t)__cvta_generic_to_shared(smem_dst);
    asm volatile("cp.async.cg.shared.global [%0], [%1], 16;\n" :: "r"(s), "l"(gmem_src));
}
#define CP_COMMIT()  asm volatile("cp.async.commit_group;\n" ::: "memory")
#define CP_WAIT(n)   asm volatile("cp.async.wait_group %0;\n" :: "n"(n) : "memory")

// ============================================================
// FP16-input GEMM (fp32 accumulate), ldmatrix fragments, 4-stage cp.async.
//   D[M,N] = epi( A[M,K] @ Bt[N,K]^T ),  A stride lda, Bt stride ldB (fp16 elems)
// flags: 1=gelu, 4=gather(addA[m/48]+addC[idx[m]]), 8=output fp16
// splitK>1: blockIdx.z = part p; A += p*Kp; Bt += p*Kp; D(fp32) += p*M*N; bias part0 only.
// splitK==1 && blockIdx.z==1: second problem (A2,Bt2,D2), no bias.
// ============================================================
#define BM 128
#define BN 128
#define BK 32
#define SROWB 80                      // bytes/row: 64B data + 16B pad
#define STAGE_B (128*SROWB)           // 10240 B
#define NSTAGE 4
#define GEMM_SMEM_BYTES (2*NSTAGE*STAGE_B)   // 81920 B

__global__ __launch_bounds__(256) void gemm_f16_kernel(
    const __half* __restrict__ A, const __half* __restrict__ Bt,
    void* __restrict__ Dv, int M, int N, int K, int lda, int ldB,
    const float* __restrict__ bias, float alpha, float beta, int flags,
    const float* __restrict__ addA, const float* __restrict__ addC,
    const int* __restrict__ idxFlat,
    const __half* __restrict__ A2, const __half* __restrict__ Bt2,
    void* __restrict__ D2, int splitK)
{
    if (splitK > 1) {
        const int part = blockIdx.z;
        const int Kp = K / splitK;
        A  += (size_t)part * Kp;
        Bt += (size_t)part * Kp;
        Dv = (void*)((float*)Dv + (size_t)part * M * N);
        if (part) bias = nullptr;
        K = Kp;
    } else if (blockIdx.z == 1) {
        A = A2; Bt = Bt2; Dv = D2; bias = nullptr;
    }

    extern __shared__ char smc[];   // [A x NSTAGE][B x NSTAGE]
    const uint32_t sbase = (uint32_t)__cvta_generic_to_shared(smc);

    const int tid  = threadIdx.x;
    const int m0   = blockIdx.x * BM;
    const int n0   = blockIdx.y * BN;
    const int warp = tid >> 5;
    const int lane = tid & 31;
    const int wm   = warp >> 1;   // 0..3
    const int wn   = warp & 1;    // 0..1
    const int gid  = lane >> 2;
    const int tig  = lane & 3;

    float acc[2][8][4];
    #pragma unroll
    for (int a = 0; a < 2; a++)
        #pragma unroll
        for (int b = 0; b < 8; b++)
            #pragma unroll
            for (int c = 0; c < 4; c++) acc[a][b][c] = 0.f;

    // ldmatrix fragment base addresses (bytes, stage 0)
    // A: lanes 0-15 -> m rows 0-15 (k0-7), lanes 16-31 -> same rows +16B (k8-15)
    const uint32_t aFrag = sbase +
        (uint32_t)((wm * 32 + (lane & 15)) * SROWB + (lane >> 4) * 16);
    // B: matrices (n0-7,k0-7),(n0-7,k8-15),(n8-15,k0-7),(n8-15,k8-15)
    const uint32_t bFrag = sbase + (uint32_t)(NSTAGE * STAGE_B) +
        (uint32_t)(((wn * 64 + ((lane >> 4) * 8) + (lane & 7)) * SROWB) +
                   (((lane >> 3) & 1) * 16));

    const __half* Abase = A  + (size_t)m0 * lda;
    const __half* Bbase = Bt + (size_t)n0 * ldB;
    const int KT = K / BK;

    auto produce = [&](int kt, int buf) {
        const __half* Ap = Abase + kt * BK;
        char* As = smc + buf * STAGE_B;
        #pragma unroll
        for (int i = 0; i < 2; i++) {
            int lin = tid + i * 256;
            int row = lin >> 2, ch = lin & 3;
            cp_async16(As + row * SROWB + ch * 16, Ap + (size_t)row * lda + ch * 8);
        }
        const __half* Bp = Bbase + kt * BK;
        char* Bs = smc + (NSTAGE + buf) * STAGE_B;
        #pragma unroll
        for (int i = 0; i < 2; i++) {
            int lin = tid + i * 256;
            int row = lin >> 2, ch = lin & 3;
            cp_async16(Bs + row * SROWB + ch * 16, Bp + (size_t)row * ldB + ch * 8);
        }
        CP_COMMIT();
    };

    const int P = KT < 3 ? KT : 3;
    for (int p = 0; p < P; p++) produce(p, p % NSTAGE);

    for (int kt = 0; kt < KT; kt++) {
        const int cur = kt % NSTAGE;
        if (kt + 3 < KT) { produce(kt + 3, (kt + 3) % NSTAGE); CP_WAIT(3); }
        else             { CP_WAIT(0); }
        __syncthreads();

        const uint32_t so = (uint32_t)(cur * STAGE_B);
        #pragma unroll
        for (int j = 0; j < 2; j++) {         // two k16 steps per BK=32
            const uint32_t aA = aFrag + so + j * 32;
            const uint32_t bA = bFrag + so + j * 32;
            uint32_t a0[4], a1[4], bf[8][2];
            LDSM_X4(a0[0], a0[1], a0[2], a0[3], aA);
            LDSM_X4(a1[0], a1[1], a1[2], a1[3], aA + 16 * SROWB);
            #pragma unroll
            for (int gg = 0; gg < 4; gg++)
                LDSM_X4(bf[2*gg][0], bf[2*gg][1], bf[2*gg+1][0], bf[2*gg+1][1],
                        bA + (uint32_t)(gg * 16 * SROWB));
            #pragma unroll
            for (int ni = 0; ni < 8; ni++) {
                mma_f16(acc[0][ni], a0, bf[ni]);
                mma_f16(acc[1][ni], a1, bf[ni]);
            }
        }
        __syncthreads();
    }

    // ---- epilogue ----
    const int doGelu = flags & 1;
    const int doGath = flags & 4;
    const int outHalf = flags & 8;
    #pragma unroll
    for (int mi = 0; mi < 2; mi++) {
        #pragma unroll
        for (int h = 0; h < 2; h++) {
            const int m = m0 + wm * 32 + mi * 16 + h * 8 + gid;
            const float* aArow = nullptr;
            const float* aCrow = nullptr;
            if (doGath) {
                aArow = addA + (size_t)(m / KNB) * N;
                aCrow = addC + (size_t)idxFlat[m] * N;
            }
            #pragma unroll
            for (int ni = 0; ni < 8; ni++) {
                const int n = n0 + wn * 64 + ni * 8 + tig * 2;
                float v0 = acc[mi][ni][h * 2 + 0] * alpha;
                float v1 = acc[mi][ni][h * 2 + 1] * alpha;
                if (bias) { v0 += beta * bias[n]; v1 += beta * bias[n + 1]; }
                if (doGath) {
                    v0 += aArow[n] + aCrow[n];
                    v1 += aArow[n + 1] + aCrow[n + 1];
                }
                if (doGelu) { v0 = gelu_exact(v0); v1 = gelu_exact(v1); }
                if (outHalf) {
                    __half2* Drow = (__half2*)((__half*)Dv + (size_t)m * N + n);
                    *Drow = __floats2half2_rn(v0, v1);
                } else {
                    float2* Drow = (float2*)((float*)Dv + (size_t)m * N + n);
                    *Drow = make_float2(v0, v1);
                }
            }
        }
    }
}

// ---------------- supporting kernels ----------------
__global__ void reduce48_kernel(const __half* __restrict__ H2, __half* __restrict__ S) {
    int i = blockIdx.x;
    int n = threadIdx.x;
    const __half* p = H2 + (size_t)i * KNB * NF + n;
    float s = 0.f;
    #pragma unroll
    for (int k = 0; k < KNB; k++) s += __half2float(p[(size_t)k * NF]);
    S[(size_t)i * NF + n] = __float2half(s);
}

// layernorm of (a + p0 [+ p1] [+ p2]); out (fp32), out2 (fp16, optional); mask optional
__global__ void ln_kernel(const float* __restrict__ a,
                          const float* __restrict__ p0,
                          const float* __restrict__ p1,
                          const float* __restrict__ p2,
                          const float* __restrict__ w, const float* __restrict__ bv,
                          const float* __restrict__ mask,
                          float* __restrict__ out, __half* __restrict__ out2)
{
    int i = blockIdx.x;
    int n = threadIdx.x;
    size_t o = (size_t)i * NF + n;
    float v = a[o] + p0[o];
    if (p1) v += p1[o];
    if (p2) v += p2[o];

    __shared__ float s1[12], s2[12];
    float x1 = v, x2 = v * v;
    #pragma unroll
    for (int off = 16; off; off >>= 1) {
        x1 += __shfl_down_sync(0xFFFFFFFFu, x1, off);
        x2 += __shfl_down_sync(0xFFFFFFFFu, x2, off);
    }
    int wi = n >> 5, li = n & 31;
    if (li == 0) { s1[wi] = x1; s2[wi] = x2; }
    __syncthreads();
    __shared__ float mean_s, rstd_s;
    if (n == 0) {
        float t1 = 0.f, t2 = 0.f;
        #pragma unroll
        for (int j = 0; j < 12; j++) { t1 += s1[j]; t2 += s2[j]; }
        float mu  = t1 * (1.f / NF);
        float var = t2 * (1.f / NF) - mu * mu;
        mean_s = mu;
        rstd_s = rsqrtf(var + 1e-5f);
    }
    __syncthreads();
    float rr = (v - mean_s) * rstd_s * w[n] + bv[n];
    if (mask) rr *= mask[i];
    out[o] = rr;
    if (out2) out2[o] = __float2half(rr);
}

__global__ void convert_half_kernel(const float* __restrict__ src,
                                    __half* __restrict__ dst, int n4) {
    int i = blockIdx.x * blockDim.x + threadIdx.x;
    if (i < n4) {
        float4 v = reinterpret_cast<const float4*>(src)[i];
        __half2* d = reinterpret_cast<__half2*>(dst + (size_t)i * 4);
        d[0] = __floats2half2_rn(v.x, v.y);
        d[1] = __floats2half2_rn(v.z, v.w);
    }
}

// node -> X (fp32 copy), Xt (fp16), NT (fp16)
__global__ void copy_round3_kernel(const float* __restrict__ src,
                                   float* __restrict__ dst,
                                   __half* __restrict__ dstR,
                                   __half* __restrict__ dstR2, int n) {
    int i = blockIdx.x * blockDim.x + threadIdx.x;
    if (i < n) {
        float v = src[i];
        __half r = __float2half(v);
        dst[i]   = v;
        dstR[i]  = r;
        dstR2[i] = r;
    }
}

// all weight transposes (fp32 [K,N] -> fp16 [N,K]) in one launch; z = type*3 + layer
__global__ void transpose_all_kernel(
    const float* __restrict__ w0,  const float* __restrict__ w1,
    const float* __restrict__ w2,  const float* __restrict__ dw0,
    const float* __restrict__ dw1,
    __half* __restrict__ w0T,  __half* __restrict__ w1T,
    __half* __restrict__ w2T,  __half* __restrict__ dw0T,
    __half* __restrict__ dw1T)
{
    const int z = blockIdx.z;
    const int type = z / 3, layer = z % 3;
    const float* in; __half* out; int K, N;
    switch (type) {
        case 0: in = w0  + (size_t)layer*MIN_*NF; out = w0T  + (size_t)layer*NF*MIN_; K = MIN_; N = NF;   break;
        case 1: in = w1  + (size_t)layer*NF*NF;   out = w1T  + (size_t)layer*NF*NF;   K = NF;   N = NF;   break;
        case 2: in = w2  + (size_t)layer*NF*NF;   out = w2T  + (size_t)layer*NF*NF;   K = NF;   N = NF;   break;
        case 3: in = dw0 + (size_t)layer*NF*MIN_; out = dw0T + (size_t)layer*MIN_*NF; K = NF;   N = MIN_; break;
        default:in = dw1 + (size_t)layer*MIN_*NF; out = dw1T + (size_t)layer*NF*MIN_; K = MIN_; N = NF;   break;
    }
    const int k0 = blockIdx.x * 32, n0 = blockIdx.y * 32;
    if (k0 >= K || n0 >= N) return;

    __shared__ float t[32][33];
    const int x = threadIdx.x, y = threadIdx.y;
    #pragma unroll
    for (int i = y; i < 32; i += 8)
        t[i][x] = in[(size_t)(k0 + i) * N + n0 + x];
    __syncthreads();
    #pragma unroll
    for (int i = y; i < 32; i += 8)
        out[(size_t)(n0 + i) * K + k0 + x] = __float2half(t[x][i]);
}

// ---------------- host orchestration ----------------
static inline void launch_gemm(const __half* A, const __half* Bt, void* D,
                               int M, int N, int K, int lda, int ldB,
                               const float* bias, float alpha, float beta, int flags,
                               const float* addA = nullptr, const float* addC = nullptr,
                               const int* idxFlat = nullptr,
                               const __half* A2 = nullptr, const __half* Bt2 = nullptr,
                               void* D2 = nullptr, int splitK = 1)
{
    dim3 grid(M / BM, N / BN, splitK > 1 ? splitK : (A2 ? 2 : 1));
    gemm_f16_kernel<<<grid, 256, GEMM_SMEM_BYTES>>>(A, Bt, D, M, N, K, lda, ldB,
                                                    bias, alpha, beta, flags,
                                                    addA, addC, idxFlat,
                                                    A2, Bt2, D2, splitK);
}

extern "C" void kernel_launch(void* const* d_in, const int* in_sizes, int n_in,
                              void* d_out, int out_size)
{
    (void)in_sizes; (void)n_in; (void)out_size;

    const float* node  = (const float*)d_in[0];
    const float* edges = (const float*)d_in[1];
    const int*   nidx  = (const int*)  d_in[2];
    const float* mask  = (const float*)d_in[3];
    const float* w0    = (const float*)d_in[4];
    const float* b0    = (const float*)d_in[5];
    const float* w1    = (const float*)d_in[6];
    const float* b1    = (const float*)d_in[7];
    const float* w2    = (const float*)d_in[8];
    const float* b2    = (const float*)d_in[9];
    const float* ln1w  = (const float*)d_in[10];
    const float* ln1b  = (const float*)d_in[11];
    const float* dw0   = (const float*)d_in[12];
    const float* db0   = (const float*)d_in[13];
    const float* dw1   = (const float*)d_in[14];
    const float* db1   = (const float*)d_in[15];
    const float* ln2w  = (const float*)d_in[16];
    const float* ln2b  = (const float*)d_in[17];

    __half *ET, *H1, *H2, *T, *Xt, *NT, *X1t, *Sb;
    __half *w0T, *w1T, *w2T, *dw0T, *dw1T;
    float *Ab, *Cb, *AGGP, *DP, *X, *X1;
    cudaGetSymbolAddress((void**)&ET,   g_ET);
    cudaGetSymbolAddress((void**)&H1,   g_H1);
    cudaGetSymbolAddress((void**)&H2,   g_H2);
    cudaGetSymbolAddress((void**)&T,    g_T);
    cudaGetSymbolAddress((void**)&Xt,   g_Xt);
    cudaGetSymbolAddress((void**)&NT,   g_NT);
    cudaGetSymbolAddress((void**)&X1t,  g_X1t);
    cudaGetSymbolAddress((void**)&Sb,   g_Sb);
    cudaGetSymbolAddress((void**)&Ab,   g_A);
    cudaGetSymbolAddress((void**)&Cb,   g_C);
    cudaGetSymbolAddress((void**)&AGGP, g_AGGP);
    cudaGetSymbolAddress((void**)&DP,   g_DP);
    cudaGetSymbolAddress((void**)&X,    g_X);
    cudaGetSymbolAddress((void**)&X1,   g_X1);
    cudaGetSymbolAddress((void**)&w0T,  g_w0T);
    cudaGetSymbolAddress((void**)&w1T,  g_w1T);
    cudaGetSymbolAddress((void**)&w2T,  g_w2T);
    cudaGetSymbolAddress((void**)&dw0T, g_dw0T);
    cudaGetSymbolAddress((void**)&dw1T, g_dw1T);

    cudaFuncSetAttribute(gemm_f16_kernel,
                         cudaFuncAttributeMaxDynamicSharedMemorySize, GEMM_SMEM_BYTES);

    // ---- preamble (3 launches) ----
    {
        int n4 = (int)((size_t)NROWS * NF / 4);
        convert_half_kernel<<<(n4 + 255) / 256, 256>>>(edges, ET, n4);
    }
    copy_round3_kernel<<<(NN * NF + 255) / 256, 256>>>(node, X, Xt, NT, NN * NF);
    transpose_all_kernel<<<dim3(48, 48, 15), dim3(32, 8)>>>(
        w0, w1, w2, dw0, dw1, w0T, w1T, w2T, dw0T, dw1T);

    for (int i = 0; i < LAYERS; i++) {
        const __half* w0L  = w0T  + (size_t)i * NF * MIN_;
        const float*  b0L  = b0   + (size_t)i * NF;
        const __half* w1L  = w1T  + (size_t)i * NF * NF;
        const float*  b1L  = b1   + (size_t)i * NF;
        const __half* w2L  = w2T  + (size_t)i * NF * NF;
        const float*  b2L  = b2   + (size_t)i * NF;
        const __half* dw0L = dw0T + (size_t)i * MIN_ * NF;
        const float*  db0L = db0  + (size_t)i * MIN_;
        const __half* dw1L = dw1T + (size_t)i * NF * MIN_;
        const float*  db1L = db1  + (size_t)i * NF;

        // (a)+(b) merged: Ab = x@W0a + b0 (fp32) ; Cb = node@W0d (fp32)
        launch_gemm(Xt, w0L, Ab, NN, NF, NF, NF, MIN_, b0L, 1.f, 1.f, 0,
                    nullptr, nullptr, nullptr,
                    NT, w0L + 1152, Cb);
        // (c) H1 = fp16(gelu(edges @ W0b + A[m/48] + C[idx]))
        launch_gemm(ET, w0L + 384, H1, NROWS, NF, NF, NF, MIN_,
                    nullptr, 1.f, 0.f, 1 | 4 | 8, Ab, Cb, nidx);
        // (d) H2 = fp16(gelu(H1 @ W1 + b1))
        launch_gemm(H1, w1L, H2, NROWS, NF, NF, NF, NF, b1L, 1.f, 1.f, 1 | 8);
        // (e) S = fp16(sum_k H2)
        reduce48_kernel<<<NN, NF>>>(H2, Sb);
        // (f) AGG parts = (S @ W2)/30 (+ (48/30) b2 in part 0), split-K=3, fp32 parts
        launch_gemm(Sb, w2L, AGGP, NN, NF, NF, NF, NF, b2L, 1.f / 30.f, 48.f / 30.f, 0,
                    nullptr, nullptr, nullptr, nullptr, nullptr, nullptr, 3);
        // (g) x1 = LN(x + sum AGG parts)
        ln_kernel<<<NN, NF>>>(X, AGGP, AGGP + (size_t)NN * NF, AGGP + (size_t)2 * NN * NF,
                              ln1w + (size_t)i * NF, ln1b + (size_t)i * NF,
                              nullptr, X1, X1t);
        // (h) T = fp16(gelu(x1 @ dense_w0 + db0))
        launch_gemm(X1t, dw0L, T, NN, MIN_, NF, NF, NF, db0L, 1.f, 1.f, 1 | 8);
        // (i) D parts = T @ dense_w1 (+ db1 in part 0), split-K=3, fp32 parts
        launch_gemm(T, dw1L, DP, NN, NF, MIN_, MIN_, MIN_, db1L, 1.f, 1.f, 0,
                    nullptr, nullptr, nullptr, nullptr, nullptr, nullptr, 3);
        // (j) x = mask * LN(x1 + sum D parts)
        float*  xout  = (i == LAYERS - 1) ? (float*)d_out : X;
        __half* xout2 = (i == LAYERS - 1) ? nullptr : Xt;
        ln_kernel<<<NN, NF>>>(X1, DP, DP + (size_t)NN * NF, DP + (size_t)2 * NN * NF,
                              ln2w + (size_t)i * NF, ln2b + (size_t)i * NF,
                              mask, xout, xout2);
    }
}

// round 10
// speedup vs baseline: 1.9319x; 1.2380x over previous
#include <cuda_runtime.h>
#include <cuda_fp16.h>
#include <cstdint>
#include <cstddef>

// ---------------- problem constants ----------------
#define NN    2048
#define KNB   48
#define NF    384
#define MIN_  1536
#define NROWS (NN*KNB)        // 98304
#define LAYERS 3

// ---------------- device scratch ----------------
__device__ __half g_ET[(size_t)NROWS * NF];
__device__ __half g_H1[(size_t)NROWS * NF];
__device__ __half g_H2[(size_t)NROWS * NF];
__device__ __half g_T [NN * MIN_];
__device__ __half g_Xt [NN * NF];
__device__ __half g_NT [NN * NF];
__device__ __half g_X1t[NN * NF];
__device__ __half g_Sb [NN * NF];
__device__ float  g_A  [NN * NF];
__device__ float  g_C  [NN * NF];
__device__ float  g_AGGP[3 * NN * NF];
__device__ float  g_DP  [3 * NN * NF];
__device__ float  g_X  [NN * NF];
__device__ float  g_X1 [NN * NF];
// transposed fp16 weights, [N][K] row-major (k-contiguous)
__device__ __half g_w0T [LAYERS * NF * MIN_];
__device__ __half g_w1T [LAYERS * NF * NF];
__device__ __half g_w2T [LAYERS * NF * NF];
__device__ __half g_dw0T[LAYERS * MIN_ * NF];
__device__ __half g_dw1T[LAYERS * NF * MIN_];

// ---------------- helpers ----------------
__device__ __forceinline__ float gelu_exact(float x) {
    return 0.5f * x * (1.0f + erff(x * 0.70710678118654752440f));
}

__device__ __forceinline__ void mma_f16(float* c, const uint32_t* a, const uint32_t* b) {
    asm volatile(
        "mma.sync.aligned.m16n8k16.row.col.f32.f16.f16.f32 "
        "{%0,%1,%2,%3}, {%4,%5,%6,%7}, {%8,%9}, {%0,%1,%2,%3};\n"
        : "+f"(c[0]), "+f"(c[1]), "+f"(c[2]), "+f"(c[3])
        : "r"(a[0]), "r"(a[1]), "r"(a[2]), "r"(a[3]),
          "r"(b[0]), "r"(b[1]));
}

#define LDSM_X4(r0, r1, r2, r3, addr) \
    asm volatile("ldmatrix.sync.aligned.m8n8.x4.shared.b16 {%0,%1,%2,%3}, [%4];" \
                 : "=r"(r0), "=r"(r1), "=r"(r2), "=r"(r3) : "r"(addr))

__device__ __forceinline__ void cp_async16(void* smem_dst, const void* gmem_src) {
    uint32_t s = (uint32_t)__cvta_generic_to_shared(smem_dst);
    asm volatile("cp.async.cg.shared.global [%0], [%1], 16;\n" :: "r"(s), "l"(gmem_src));
}
#define CP_COMMIT()  asm volatile("cp.async.commit_group;\n" ::: "memory")
#define CP_WAIT(n)   asm volatile("cp.async.wait_group %0;\n" :: "n"(n) : "memory")

// ============================================================
// FP16-input GEMM (fp32 accumulate), ldmatrix fragments, 4-stage cp.async,
// 2 CTAs/SM (forced via launch bounds, regs <= 128).
//   D[M,N] = epi( A[M,K] @ Bt[N,K]^T ),  A stride lda, Bt stride ldB (fp16 elems)
// flags: 1=gelu, 4=gather(addA[m/48]+addC[idx[m]]), 8=output fp16
// splitK>1: blockIdx.z = part p; A += p*Kp; Bt += p*Kp; D(fp32) += p*M*N; bias part0 only.
// splitK==1 && blockIdx.z==1: second problem (A2,Bt2,D2), no bias.
// ============================================================
#define BM 128
#define BN 128
#define BK 32
#define SROWB 80                      // bytes/row: 64B data + 16B pad
#define STAGE_B (128*SROWB)           // 10240 B
#define NSTAGE 4
#define GEMM_SMEM_BYTES (2*NSTAGE*STAGE_B)   // 81920 B; x2 CTAs = 160KB < 228KB

__global__ __launch_bounds__(256, 2) void gemm_f16_kernel(
    const __half* __restrict__ A, const __half* __restrict__ Bt,
    void* __restrict__ Dv, int M, int N, int K, int lda, int ldB,
    const float* __restrict__ bias, float alpha, float beta, int flags,
    const float* __restrict__ addA, const float* __restrict__ addC,
    const int* __restrict__ idxFlat,
    const __half* __restrict__ A2, const __half* __restrict__ Bt2,
    void* __restrict__ D2, int splitK)
{
    if (splitK > 1) {
        const int part = blockIdx.z;
        const int Kp = K / splitK;
        A  += (size_t)part * Kp;
        Bt += (size_t)part * Kp;
        Dv = (void*)((float*)Dv + (size_t)part * M * N);
        if (part) bias = nullptr;
        K = Kp;
    } else if (blockIdx.z == 1) {
        A = A2; Bt = Bt2; Dv = D2; bias = nullptr;
    }

    extern __shared__ char smc[];   // [A x NSTAGE][B x NSTAGE]
    const uint32_t sbase = (uint32_t)__cvta_generic_to_shared(smc);

    const int tid  = threadIdx.x;
    const int m0   = blockIdx.x * BM;
    const int n0   = blockIdx.y * BN;
    const int warp = tid >> 5;
    const int lane = tid & 31;
    const int wm   = warp >> 1;   // 0..3
    const int wn   = warp & 1;    // 0..1
    const int gid  = lane >> 2;
    const int tig  = lane & 3;

    float acc[2][8][4];
    #pragma unroll
    for (int a = 0; a < 2; a++)
        #pragma unroll
        for (int b = 0; b < 8; b++)
            #pragma unroll
            for (int c = 0; c < 4; c++) acc[a][b][c] = 0.f;

    // ldmatrix fragment base addresses (bytes, stage 0)
    const uint32_t aFrag = sbase +
        (uint32_t)((wm * 32 + (lane & 15)) * SROWB + (lane >> 4) * 16);
    const uint32_t bFrag = sbase + (uint32_t)(NSTAGE * STAGE_B) +
        (uint32_t)(((wn * 64 + ((lane >> 4) * 8) + (lane & 7)) * SROWB) +
                   (((lane >> 3) & 1) * 16));

    const __half* Abase = A  + (size_t)m0 * lda;
    const __half* Bbase = Bt + (size_t)n0 * ldB;
    const int KT = K / BK;

    auto produce = [&](int kt, int buf) {
        const __half* Ap = Abase + kt * BK;
        char* As = smc + buf * STAGE_B;
        #pragma unroll
        for (int i = 0; i < 2; i++) {
            int lin = tid + i * 256;
            int row = lin >> 2, ch = lin & 3;
            cp_async16(As + row * SROWB + ch * 16, Ap + (size_t)row * lda + ch * 8);
        }
        const __half* Bp = Bbase + kt * BK;
        char* Bs = smc + (NSTAGE + buf) * STAGE_B;
        #pragma unroll
        for (int i = 0; i < 2; i++) {
            int lin = tid + i * 256;
            int row = lin >> 2, ch = lin & 3;
            cp_async16(Bs + row * SROWB + ch * 16, Bp + (size_t)row * ldB + ch * 8);
        }
        CP_COMMIT();
    };

    const int P = KT < 3 ? KT : 3;
    for (int p = 0; p < P; p++) produce(p, p % NSTAGE);

    for (int kt = 0; kt < KT; kt++) {
        const int cur = kt % NSTAGE;
        if (kt + 3 < KT) { produce(kt + 3, (kt + 3) % NSTAGE); CP_WAIT(3); }
        else             { CP_WAIT(0); }
        __syncthreads();

        const uint32_t so = (uint32_t)(cur * STAGE_B);
        #pragma unroll
        for (int j = 0; j < 2; j++) {         // two k16 steps per BK=32
            const uint32_t aA = aFrag + so + j * 32;
            const uint32_t bA = bFrag + so + j * 32;
            uint32_t a0[4], a1[4], bf[8][2];
            LDSM_X4(a0[0], a0[1], a0[2], a0[3], aA);
            LDSM_X4(a1[0], a1[1], a1[2], a1[3], aA + 16 * SROWB);
            #pragma unroll
            for (int gg = 0; gg < 4; gg++)
                LDSM_X4(bf[2*gg][0], bf[2*gg][1], bf[2*gg+1][0], bf[2*gg+1][1],
                        bA + (uint32_t)(gg * 16 * SROWB));
            #pragma unroll
            for (int ni = 0; ni < 8; ni++) {
                mma_f16(acc[0][ni], a0, bf[ni]);
                mma_f16(acc[1][ni], a1, bf[ni]);
            }
        }
        __syncthreads();
    }

    // ---- epilogue ----
    const int doGelu = flags & 1;
    const int doGath = flags & 4;
    const int outHalf = flags & 8;
    #pragma unroll
    for (int mi = 0; mi < 2; mi++) {
        #pragma unroll
        for (int h = 0; h < 2; h++) {
            const int m = m0 + wm * 32 + mi * 16 + h * 8 + gid;
            const float* aArow = nullptr;
            const float* aCrow = nullptr;
            if (doGath) {
                aArow = addA + (size_t)(m / KNB) * N;
                aCrow = addC + (size_t)idxFlat[m] * N;
            }
            #pragma unroll
            for (int ni = 0; ni < 8; ni++) {
                const int n = n0 + wn * 64 + ni * 8 + tig * 2;
                float v0 = acc[mi][ni][h * 2 + 0] * alpha;
                float v1 = acc[mi][ni][h * 2 + 1] * alpha;
                if (bias) { v0 += beta * bias[n]; v1 += beta * bias[n + 1]; }
                if (doGath) {
                    v0 += aArow[n] + aCrow[n];
                    v1 += aArow[n + 1] + aCrow[n + 1];
                }
                if (doGelu) { v0 = gelu_exact(v0); v1 = gelu_exact(v1); }
                if (outHalf) {
                    __half2* Drow = (__half2*)((__half*)Dv + (size_t)m * N + n);
                    *Drow = __floats2half2_rn(v0, v1);
                } else {
                    float2* Drow = (float2*)((float*)Dv + (size_t)m * N + n);
                    *Drow = make_float2(v0, v1);
                }
            }
        }
    }
}

// ---------------- supporting kernels ----------------
__global__ void reduce48_kernel(const __half* __restrict__ H2, __half* __restrict__ S) {
    int i = blockIdx.x;
    int n = threadIdx.x;
    const __half* p = H2 + (size_t)i * KNB * NF + n;
    float s = 0.f;
    #pragma unroll
    for (int k = 0; k < KNB; k++) s += __half2float(p[(size_t)k * NF]);
    S[(size_t)i * NF + n] = __float2half(s);
}

// layernorm of (a + p0 [+ p1] [+ p2]); out (fp32), out2 (fp16, optional); mask optional
__global__ void ln_kernel(const float* __restrict__ a,
                          const float* __restrict__ p0,
                          const float* __restrict__ p1,
                          const float* __restrict__ p2,
                          const float* __restrict__ w, const float* __restrict__ bv,
                          const float* __restrict__ mask,
                          float* __restrict__ out, __half* __restrict__ out2)
{
    int i = blockIdx.x;
    int n = threadIdx.x;
    size_t o = (size_t)i * NF + n;
    float v = a[o] + p0[o];
    if (p1) v += p1[o];
    if (p2) v += p2[o];

    __shared__ float s1[12], s2[12];
    float x1 = v, x2 = v * v;
    #pragma unroll
    for (int off = 16; off; off >>= 1) {
        x1 += __shfl_down_sync(0xFFFFFFFFu, x1, off);
        x2 += __shfl_down_sync(0xFFFFFFFFu, x2, off);
    }
    int wi = n >> 5, li = n & 31;
    if (li == 0) { s1[wi] = x1; s2[wi] = x2; }
    __syncthreads();
    __shared__ float mean_s, rstd_s;
    if (n == 0) {
        float t1 = 0.f, t2 = 0.f;
        #pragma unroll
        for (int j = 0; j < 12; j++) { t1 += s1[j]; t2 += s2[j]; }
        float mu  = t1 * (1.f / NF);
        float var = t2 * (1.f / NF) - mu * mu;
        mean_s = mu;
        rstd_s = rsqrtf(var + 1e-5f);
    }
    __syncthreads();
    float rr = (v - mean_s) * rstd_s * w[n] + bv[n];
    if (mask) rr *= mask[i];
    out[o] = rr;
    if (out2) out2[o] = __float2half(rr);
}

__global__ void convert_half_kernel(const float* __restrict__ src,
                                    __half* __restrict__ dst, int n4) {
    int i = blockIdx.x * blockDim.x + threadIdx.x;
    if (i < n4) {
        float4 v = reinterpret_cast<const float4*>(src)[i];
        __half2* d = reinterpret_cast<__half2*>(dst + (size_t)i * 4);
        d[0] = __floats2half2_rn(v.x, v.y);
        d[1] = __floats2half2_rn(v.z, v.w);
    }
}

// node -> X (fp32 copy), Xt (fp16), NT (fp16)
__global__ void copy_round3_kernel(const float* __restrict__ src,
                                   float* __restrict__ dst,
                                   __half* __restrict__ dstR,
                                   __half* __restrict__ dstR2, int n) {
    int i = blockIdx.x * blockDim.x + threadIdx.x;
    if (i < n) {
        float v = src[i];
        __half r = __float2half(v);
        dst[i]   = v;
        dstR[i]  = r;
        dstR2[i] = r;
    }
}

// all weight transposes (fp32 [K,N] -> fp16 [N,K]) in one launch; z = type*3 + layer
__global__ void transpose_all_kernel(
    const float* __restrict__ w0,  const float* __restrict__ w1,
    const float* __restrict__ w2,  const float* __restrict__ dw0,
    const float* __restrict__ dw1,
    __half* __restrict__ w0T,  __half* __restrict__ w1T,
    __half* __restrict__ w2T,  __half* __restrict__ dw0T,
    __half* __restrict__ dw1T)
{
    const int z = blockIdx.z;
    const int type = z / 3, layer = z % 3;
    const float* in; __half* out; int K, N;
    switch (type) {
        case 0: in = w0  + (size_t)layer*MIN_*NF; out = w0T  + (size_t)layer*NF*MIN_; K = MIN_; N = NF;   break;
        case 1: in = w1  + (size_t)layer*NF*NF;   out = w1T  + (size_t)layer*NF*NF;   K = NF;   N = NF;   break;
        case 2: in = w2  + (size_t)layer*NF*NF;   out = w2T  + (size_t)layer*NF*NF;   K = NF;   N = NF;   break;
        case 3: in = dw0 + (size_t)layer*NF*MIN_; out = dw0T + (size_t)layer*MIN_*NF; K = NF;   N = MIN_; break;
        default:in = dw1 + (size_t)layer*MIN_*NF; out = dw1T + (size_t)layer*NF*MIN_; K = MIN_; N = NF;   break;
    }
    const int k0 = blockIdx.x * 32, n0 = blockIdx.y * 32;
    if (k0 >= K || n0 >= N) return;

    __shared__ float t[32][33];
    const int x = threadIdx.x, y = threadIdx.y;
    #pragma unroll
    for (int i = y; i < 32; i += 8)
        t[i][x] = in[(size_t)(k0 + i) * N + n0 + x];
    __syncthreads();
    #pragma unroll
    for (int i = y; i < 32; i += 8)
        out[(size_t)(n0 + i) * K + k0 + x] = __float2half(t[x][i]);
}

// ---------------- host orchestration ----------------
static inline void launch_gemm(const __half* A, const __half* Bt, void* D,
                               int M, int N, int K, int lda, int ldB,
                               const float* bias, float alpha, float beta, int flags,
                               const float* addA = nullptr, const float* addC = nullptr,
                               const int* idxFlat = nullptr,
                               const __half* A2 = nullptr, const __half* Bt2 = nullptr,
                               void* D2 = nullptr, int splitK = 1)
{
    dim3 grid(M / BM, N / BN, splitK > 1 ? splitK : (A2 ? 2 : 1));
    gemm_f16_kernel<<<grid, 256, GEMM_SMEM_BYTES>>>(A, Bt, D, M, N, K, lda, ldB,
                                                    bias, alpha, beta, flags,
                                                    addA, addC, idxFlat,
                                                    A2, Bt2, D2, splitK);
}

extern "C" void kernel_launch(void* const* d_in, const int* in_sizes, int n_in,
                              void* d_out, int out_size)
{
    (void)in_sizes; (void)n_in; (void)out_size;

    const float* node  = (const float*)d_in[0];
    const float* edges = (const float*)d_in[1];
    const int*   nidx  = (const int*)  d_in[2];
    const float* mask  = (const float*)d_in[3];
    const float* w0    = (const float*)d_in[4];
    const float* b0    = (const float*)d_in[5];
    const float* w1    = (const float*)d_in[6];
    const float* b1    = (const float*)d_in[7];
    const float* w2    = (const float*)d_in[8];
    const float* b2    = (const float*)d_in[9];
    const float* ln1w  = (const float*)d_in[10];
    const float* ln1b  = (const float*)d_in[11];
    const float* dw0   = (const float*)d_in[12];
    const float* db0   = (const float*)d_in[13];
    const float* dw1   = (const float*)d_in[14];
    const float* db1   = (const float*)d_in[15];
    const float* ln2w  = (const float*)d_in[16];
    const float* ln2b  = (const float*)d_in[17];

    __half *ET, *H1, *H2, *T, *Xt, *NT, *X1t, *Sb;
    __half *w0T, *w1T, *w2T, *dw0T, *dw1T;
    float *Ab, *Cb, *AGGP, *DP, *X, *X1;
    cudaGetSymbolAddress((void**)&ET,   g_ET);
    cudaGetSymbolAddress((void**)&H1,   g_H1);
    cudaGetSymbolAddress((void**)&H2,   g_H2);
    cudaGetSymbolAddress((void**)&T,    g_T);
    cudaGetSymbolAddress((void**)&Xt,   g_Xt);
    cudaGetSymbolAddress((void**)&NT,   g_NT);
    cudaGetSymbolAddress((void**)&X1t,  g_X1t);
    cudaGetSymbolAddress((void**)&Sb,   g_Sb);
    cudaGetSymbolAddress((void**)&Ab,   g_A);
    cudaGetSymbolAddress((void**)&Cb,   g_C);
    cudaGetSymbolAddress((void**)&AGGP, g_AGGP);
    cudaGetSymbolAddress((void**)&DP,   g_DP);
    cudaGetSymbolAddress((void**)&X,    g_X);
    cudaGetSymbolAddress((void**)&X1,   g_X1);
    cudaGetSymbolAddress((void**)&w0T,  g_w0T);
    cudaGetSymbolAddress((void**)&w1T,  g_w1T);
    cudaGetSymbolAddress((void**)&w2T,  g_w2T);
    cudaGetSymbolAddress((void**)&dw0T, g_dw0T);
    cudaGetSymbolAddress((void**)&dw1T, g_dw1T);

    cudaFuncSetAttribute(gemm_f16_kernel,
                         cudaFuncAttributeMaxDynamicSharedMemorySize, GEMM_SMEM_BYTES);

    // ---- preamble (3 launches) ----
    {
        int n4 = (int)((size_t)NROWS * NF / 4);
        convert_half_kernel<<<(n4 + 255) / 256, 256>>>(edges, ET, n4);
    }
    copy_round3_kernel<<<(NN * NF + 255) / 256, 256>>>(node, X, Xt, NT, NN * NF);
    transpose_all_kernel<<<dim3(48, 48, 15), dim3(32, 8)>>>(
        w0, w1, w2, dw0, dw1, w0T, w1T, w2T, dw0T, dw1T);

    for (int i = 0; i < LAYERS; i++) {
        const __half* w0L  = w0T  + (size_t)i * NF * MIN_;
        const float*  b0L  = b0   + (size_t)i * NF;
        const __half* w1L  = w1T  + (size_t)i * NF * NF;
        const float*  b1L  = b1   + (size_t)i * NF;
        const __half* w2L  = w2T  + (size_t)i * NF * NF;
        const float*  b2L  = b2   + (size_t)i * NF;
        const __half* dw0L = dw0T + (size_t)i * MIN_ * NF;
        const float*  db0L = db0  + (size_t)i * MIN_;
        const __half* dw1L = dw1T + (size_t)i * NF * MIN_;
        const float*  db1L = db1  + (size_t)i * NF;

        // (a)+(b) merged: Ab = x@W0a + b0 (fp32) ; Cb = node@W0d (fp32)
        launch_gemm(Xt, w0L, Ab, NN, NF, NF, NF, MIN_, b0L, 1.f, 1.f, 0,
                    nullptr, nullptr, nullptr,
                    NT, w0L + 1152, Cb);
        // (c) H1 = fp16(gelu(edges @ W0b + A[m/48] + C[idx]))
        launch_gemm(ET, w0L + 384, H1, NROWS, NF, NF, NF, MIN_,
                    nullptr, 1.f, 0.f, 1 | 4 | 8, Ab, Cb, nidx);
        // (d) H2 = fp16(gelu(H1 @ W1 + b1))
        launch_gemm(H1, w1L, H2, NROWS, NF, NF, NF, NF, b1L, 1.f, 1.f, 1 | 8);
        // (e) S = fp16(sum_k H2)
        reduce48_kernel<<<NN, NF>>>(H2, Sb);
        // (f) AGG parts = (S @ W2)/30 (+ (48/30) b2 in part 0), split-K=3, fp32 parts
        launch_gemm(Sb, w2L, AGGP, NN, NF, NF, NF, NF, b2L, 1.f / 30.f, 48.f / 30.f, 0,
                    nullptr, nullptr, nullptr, nullptr, nullptr, nullptr, 3);
        // (g) x1 = LN(x + sum AGG parts)
        ln_kernel<<<NN, NF>>>(X, AGGP, AGGP + (size_t)NN * NF, AGGP + (size_t)2 * NN * NF,
                              ln1w + (size_t)i * NF, ln1b + (size_t)i * NF,
                              nullptr, X1, X1t);
        // (h) T = fp16(gelu(x1 @ dense_w0 + db0))
        launch_gemm(X1t, dw0L, T, NN, MIN_, NF, NF, NF, db0L, 1.f, 1.f, 1 | 8);
        // (i) D parts = T @ dense_w1 (+ db1 in part 0), split-K=3, fp32 parts
        launch_gemm(T, dw1L, DP, NN, NF, MIN_, MIN_, MIN_, db1L, 1.f, 1.f, 0,
                    nullptr, nullptr, nullptr, nullptr, nullptr, nullptr, 3);
        // (j) x = mask * LN(x1 + sum D parts)
        float*  xout  = (i == LAYERS - 1) ? (float*)d_out : X;
        __half* xout2 = (i == LAYERS - 1) ? nullptr : Xt;
        ln_kernel<<<NN, NF>>>(X1, DP, DP + (size_t)NN * NF, DP + (size_t)2 * NN * NF,
                              ln2w + (size_t)i * NF, ln2b + (size_t)i * NF,
                              mask, xout, xout2);
    }
}

// round 11
// speedup vs baseline: 1.9613x; 1.0153x over previous
#include <cuda_runtime.h>
#include <cuda_fp16.h>
#include <cstdint>
#include <cstddef>

// ---------------- problem constants ----------------
#define NN    2048
#define KNB   48
#define NF    384
#define MIN_  1536
#define NROWS (NN*KNB)        // 98304
#define LAYERS 3

// ---------------- device scratch ----------------
__device__ __half g_ET[(size_t)NROWS * NF];
__device__ __half g_H1[(size_t)NROWS * NF];
__device__ __half g_H2[(size_t)NROWS * NF];
__device__ __half g_T [NN * MIN_];
__device__ __half g_Xt [NN * NF];
__device__ __half g_NT [NN * NF];
__device__ __half g_X1t[NN * NF];
__device__ __half g_Sb [NN * NF];
__device__ float  g_A  [NN * NF];
__device__ float  g_C  [NN * NF];
__device__ float  g_AGGP[3 * NN * NF];
__device__ float  g_DP  [3 * NN * NF];
__device__ float  g_X  [NN * NF];
__device__ float  g_X1 [NN * NF];
// transposed fp16 weights, [N][K] row-major (k-contiguous)
__device__ __half g_w0T [LAYERS * NF * MIN_];
__device__ __half g_w1T [LAYERS * NF * NF];
__device__ __half g_w2T [LAYERS * NF * NF];
__device__ __half g_dw0T[LAYERS * MIN_ * NF];
__device__ __half g_dw1T[LAYERS * NF * MIN_];

// ---------------- helpers ----------------
__device__ __forceinline__ float gelu_exact(float x) {
    return 0.5f * x * (1.0f + erff(x * 0.70710678118654752440f));
}

__device__ __forceinline__ void mma_f16(float* c, const uint32_t* a, const uint32_t* b) {
    asm volatile(
        "mma.sync.aligned.m16n8k16.row.col.f32.f16.f16.f32 "
        "{%0,%1,%2,%3}, {%4,%5,%6,%7}, {%8,%9}, {%0,%1,%2,%3};\n"
        : "+f"(c[0]), "+f"(c[1]), "+f"(c[2]), "+f"(c[3])
        : "r"(a[0]), "r"(a[1]), "r"(a[2]), "r"(a[3]),
          "r"(b[0]), "r"(b[1]));
}

#define LDSM_X4(r0, r1, r2, r3, addr) \
    asm volatile("ldmatrix.sync.aligned.m8n8.x4.shared.b16 {%0,%1,%2,%3}, [%4];" \
                 : "=r"(r0), "=r"(r1), "=r"(r2), "=r"(r3) : "r"(addr))

__device__ __forceinline__ void cp_async16(void* smem_dst, const void* gmem_src) {
    uint32_t s = (uint32_t)__cvta_generic_to_shared(smem_dst);
    asm volatile("cp.async.cg.shared.global [%0], [%1], 16;\n" :: "r"(s), "l"(gmem_src));
}
#define CP_COMMIT()  asm volatile("cp.async.commit_group;\n" ::: "memory")
#define CP_WAIT(n)   asm volatile("cp.async.wait_group %0;\n" :: "n"(n) : "memory")

// ============================================================
// FP16-input GEMM (fp32 acc), ldmatrix fragments, 4-stage cp.async,
// ONE __syncthreads per K-iter, 2 CTAs/SM.
// Template NWM = warps along M (4 -> BM=128, 2 -> BM=64). BN=128 fixed.
//   D[M,N] = epi( A[M,K] @ Bt[N,K]^T ), A stride lda, Bt stride ldB.
// flags: 1=gelu, 4=gather(addA[m/48]+addC[idx[m]]), 8=output fp16
// splitK>1: blockIdx.z = part p (fp32 parts at D + p*M*N, bias part0 only)
// splitK==1 && blockIdx.z==1: second problem (A2,Bt2,D2), no bias.
// ============================================================
#define BK 32
#define SROWB 80                      // bytes/row: 64B data + 16B pad
#define STAGE_B (128*SROWB)           // 10240 B (A region sized for 128 rows)
#define NSTAGE 4
#define GEMM_SMEM_BYTES (2*NSTAGE*STAGE_B)   // 81920 B; x2 CTAs = 160KB

template<int NWM>
__global__ __launch_bounds__(256, 2) void gemm_f16_kernel(
    const __half* __restrict__ A, const __half* __restrict__ Bt,
    void* __restrict__ Dv, int M, int N, int K, int lda, int ldB,
    const float* __restrict__ bias, float alpha, float beta, int flags,
    const float* __restrict__ addA, const float* __restrict__ addC,
    const int* __restrict__ idxFlat,
    const __half* __restrict__ A2, const __half* __restrict__ Bt2,
    void* __restrict__ D2, int splitK)
{
    constexpr int BM_   = NWM * 32;
    constexpr int NWN   = 8 / NWM;
    constexpr int NCOLS = 128 / NWN;      // per-warp n columns
    constexpr int NI    = NCOLS / 8;      // 8 or 4

    if (splitK > 1) {
        const int part = blockIdx.z;
        const int Kp = K / splitK;
        A  += (size_t)part * Kp;
        Bt += (size_t)part * Kp;
        Dv = (void*)((float*)Dv + (size_t)part * M * N);
        if (part) bias = nullptr;
        K = Kp;
    } else if (blockIdx.z == 1) {
        A = A2; Bt = Bt2; Dv = D2; bias = nullptr;
    }

    extern __shared__ char smc[];   // [A x NSTAGE][B x NSTAGE]
    const uint32_t sbase = (uint32_t)__cvta_generic_to_shared(smc);

    const int tid  = threadIdx.x;
    const int m0   = blockIdx.x * BM_;
    const int n0   = blockIdx.y * 128;
    const int warp = tid >> 5;
    const int lane = tid & 31;
    const int wm   = warp / NWN;
    const int wn   = warp % NWN;
    const int gid  = lane >> 2;
    const int tig  = lane & 3;

    float acc[2][NI][4];
    #pragma unroll
    for (int a = 0; a < 2; a++)
        #pragma unroll
        for (int b = 0; b < NI; b++)
            #pragma unroll
            for (int c = 0; c < 4; c++) acc[a][b][c] = 0.f;

    // ldmatrix fragment base addresses (bytes, stage 0)
    const uint32_t aFrag = sbase +
        (uint32_t)((wm * 32 + (lane & 15)) * SROWB + (lane >> 4) * 16);
    const uint32_t bFrag = sbase + (uint32_t)(NSTAGE * STAGE_B) +
        (uint32_t)(((wn * NCOLS + ((lane >> 4) * 8) + (lane & 7)) * SROWB) +
                   (((lane >> 3) & 1) * 16));

    const __half* Abase = A  + (size_t)m0 * lda;
    const __half* Bbase = Bt + (size_t)n0 * ldB;
    const int KT = K / BK;

    auto produce = [&](int kt, int buf) {
        const __half* Ap = Abase + kt * BK;
        char* As = smc + buf * STAGE_B;
        #pragma unroll
        for (int i = 0; i < BM_ * 4 / 256; i++) {
            int lin = tid + i * 256;
            int row = lin >> 2, ch = lin & 3;
            cp_async16(As + row * SROWB + ch * 16, Ap + (size_t)row * lda + ch * 8);
        }
        const __half* Bp = Bbase + kt * BK;
        char* Bs = smc + (NSTAGE + buf) * STAGE_B;
        #pragma unroll
        for (int i = 0; i < 2; i++) {
            int lin = tid + i * 256;
            int row = lin >> 2, ch = lin & 3;
            cp_async16(Bs + row * SROWB + ch * 16, Bp + (size_t)row * ldB + ch * 8);
        }
        CP_COMMIT();
    };

    const int P = KT < 3 ? KT : 3;
    for (int p = 0; p < P; p++) produce(p, p % NSTAGE);

    for (int kt = 0; kt < KT; kt++) {
        const int cur = kt % NSTAGE;
        // allow = min(2, KT-kt-1) incomplete newest groups
        if (kt + 3 <= KT)      { CP_WAIT(2); }
        else if (kt + 2 == KT) { CP_WAIT(1); }
        else                   { CP_WAIT(0); }
        __syncthreads();

        const uint32_t so = (uint32_t)(cur * STAGE_B);
        #pragma unroll
        for (int j = 0; j < 2; j++) {         // two k16 steps per BK=32
            const uint32_t aA = aFrag + so + j * 32;
            const uint32_t bA = bFrag + so + j * 32;
            uint32_t a0[4], a1[4], bf[NI][2];
            LDSM_X4(a0[0], a0[1], a0[2], a0[3], aA);
            LDSM_X4(a1[0], a1[1], a1[2], a1[3], aA + 16 * SROWB);
            #pragma unroll
            for (int gg = 0; gg < NI / 2; gg++)
                LDSM_X4(bf[2*gg][0], bf[2*gg][1], bf[2*gg+1][0], bf[2*gg+1][1],
                        bA + (uint32_t)(gg * 16 * SROWB));
            #pragma unroll
            for (int ni = 0; ni < NI; ni++) {
                mma_f16(acc[0][ni], a0, bf[ni]);
                mma_f16(acc[1][ni], a1, bf[ni]);
            }
        }
        // produce AFTER barrier: stage (kt+3)%4 == (kt-1)%4, whose readers
        // all finished before this iteration's __syncthreads.
        if (kt + 3 < KT) produce(kt + 3, (kt + 3) % NSTAGE);
    }

    // ---- epilogue ----
    const int doGelu = flags & 1;
    const int doGath = flags & 4;
    const int outHalf = flags & 8;
    #pragma unroll
    for (int mi = 0; mi < 2; mi++) {
        #pragma unroll
        for (int h = 0; h < 2; h++) {
            const int m = m0 + wm * 32 + mi * 16 + h * 8 + gid;
            const float* aArow = nullptr;
            const float* aCrow = nullptr;
            if (doGath) {
                aArow = addA + (size_t)(m / KNB) * N;
                aCrow = addC + (size_t)idxFlat[m] * N;
            }
            #pragma unroll
            for (int ni = 0; ni < NI; ni++) {
                const int n = n0 + wn * NCOLS + ni * 8 + tig * 2;
                float v0 = acc[mi][ni][h * 2 + 0] * alpha;
                float v1 = acc[mi][ni][h * 2 + 1] * alpha;
                if (bias) { v0 += beta * bias[n]; v1 += beta * bias[n + 1]; }
                if (doGath) {
                    v0 += aArow[n] + aCrow[n];
                    v1 += aArow[n + 1] + aCrow[n + 1];
                }
                if (doGelu) { v0 = gelu_exact(v0); v1 = gelu_exact(v1); }
                if (outHalf) {
                    __half2* Drow = (__half2*)((__half*)Dv + (size_t)m * N + n);
                    *Drow = __floats2half2_rn(v0, v1);
                } else {
                    float2* Drow = (float2*)((float*)Dv + (size_t)m * N + n);
                    *Drow = make_float2(v0, v1);
                }
            }
        }
    }
}

// ---------------- supporting kernels ----------------
__global__ void reduce48_kernel(const __half* __restrict__ H2, __half* __restrict__ S) {
    int i = blockIdx.x;
    int n = threadIdx.x;
    const __half* p = H2 + (size_t)i * KNB * NF + n;
    float s = 0.f;
    #pragma unroll
    for (int k = 0; k < KNB; k++) s += __half2float(p[(size_t)k * NF]);
    S[(size_t)i * NF + n] = __float2half(s);
}

// layernorm of (a + p0 [+ p1] [+ p2]); out (fp32), out2 (fp16, optional); mask optional
__global__ void ln_kernel(const float* __restrict__ a,
                          const float* __restrict__ p0,
                          const float* __restrict__ p1,
                          const float* __restrict__ p2,
                          const float* __restrict__ w, const float* __restrict__ bv,
                          const float* __restrict__ mask,
                          float* __restrict__ out, __half* __restrict__ out2)
{
    int i = blockIdx.x;
    int n = threadIdx.x;
    size_t o = (size_t)i * NF + n;
    float v = a[o] + p0[o];
    if (p1) v += p1[o];
    if (p2) v += p2[o];

    __shared__ float s1[12], s2[12];
    float x1 = v, x2 = v * v;
    #pragma unroll
    for (int off = 16; off; off >>= 1) {
        x1 += __shfl_down_sync(0xFFFFFFFFu, x1, off);
        x2 += __shfl_down_sync(0xFFFFFFFFu, x2, off);
    }
    int wi = n >> 5, li = n & 31;
    if (li == 0) { s1[wi] = x1; s2[wi] = x2; }
    __syncthreads();
    __shared__ float mean_s, rstd_s;
    if (n == 0) {
        float t1 = 0.f, t2 = 0.f;
        #pragma unroll
        for (int j = 0; j < 12; j++) { t1 += s1[j]; t2 += s2[j]; }
        float mu  = t1 * (1.f / NF);
        float var = t2 * (1.f / NF) - mu * mu;
        mean_s = mu;
        rstd_s = rsqrtf(var + 1e-5f);
    }
    __syncthreads();
    float rr = (v - mean_s) * rstd_s * w[n] + bv[n];
    if (mask) rr *= mask[i];
    out[o] = rr;
    if (out2) out2[o] = __float2half(rr);
}

// merged preamble: edges fp32->fp16 AND node -> X(fp32), Xt(fp16), NT(fp16)
#define N4E ((size_t)NROWS * NF / 4)
#define N4N (NN * NF / 4)
__global__ void prep_kernel(const float* __restrict__ edges, __half* __restrict__ ET,
                            const float* __restrict__ node, float* __restrict__ X,
                            __half* __restrict__ Xt, __half* __restrict__ NT)
{
    size_t i = (size_t)blockIdx.x * blockDim.x + threadIdx.x;
    if (i < N4E) {
        float4 v = reinterpret_cast<const float4*>(edges)[i];
        __half2* d = reinterpret_cast<__half2*>(ET + i * 4);
        d[0] = __floats2half2_rn(v.x, v.y);
        d[1] = __floats2half2_rn(v.z, v.w);
    }
    if (i < N4N) {
        float4 v = reinterpret_cast<const float4*>(node)[i];
        reinterpret_cast<float4*>(X)[i] = v;
        __half2 h0 = __floats2half2_rn(v.x, v.y);
        __half2 h1 = __floats2half2_rn(v.z, v.w);
        __half2* xt = reinterpret_cast<__half2*>(Xt + i * 4);
        __half2* nt = reinterpret_cast<__half2*>(NT + i * 4);
        xt[0] = h0; xt[1] = h1;
        nt[0] = h0; nt[1] = h1;
    }
}

// all weight transposes (fp32 [K,N] -> fp16 [N,K]) in one launch; z = type*3 + layer
__global__ void transpose_all_kernel(
    const float* __restrict__ w0,  const float* __restrict__ w1,
    const float* __restrict__ w2,  const float* __restrict__ dw0,
    const float* __restrict__ dw1,
    __half* __restrict__ w0T,  __half* __restrict__ w1T,
    __half* __restrict__ w2T,  __half* __restrict__ dw0T,
    __half* __restrict__ dw1T)
{
    const int z = blockIdx.z;
    const int type = z / 3, layer = z % 3;
    const float* in; __half* out; int K, N;
    switch (type) {
        case 0: in = w0  + (size_t)layer*MIN_*NF; out = w0T  + (size_t)layer*NF*MIN_; K = MIN_; N = NF;   break;
        case 1: in = w1  + (size_t)layer*NF*NF;   out = w1T  + (size_t)layer*NF*NF;   K = NF;   N = NF;   break;
        case 2: in = w2  + (size_t)layer*NF*NF;   out = w2T  + (size_t)layer*NF*NF;   K = NF;   N = NF;   break;
        case 3: in = dw0 + (size_t)layer*NF*MIN_; out = dw0T + (size_t)layer*MIN_*NF; K = NF;   N = MIN_; break;
        default:in = dw1 + (size_t)layer*MIN_*NF; out = dw1T + (size_t)layer*NF*MIN_; K = MIN_; N = NF;   break;
    }
    const int k0 = blockIdx.x * 32, n0 = blockIdx.y * 32;
    if (k0 >= K || n0 >= N) return;

    __shared__ float t[32][33];
    const int x = threadIdx.x, y = threadIdx.y;
    #pragma unroll
    for (int i = y; i < 32; i += 8)
        t[i][x] = in[(size_t)(k0 + i) * N + n0 + x];
    __syncthreads();
    #pragma unroll
    for (int i = y; i < 32; i += 8)
        out[(size_t)(n0 + i) * K + k0 + x] = __float2half(t[x][i]);
}

// ---------------- host orchestration ----------------
static inline void launch_gemm(bool smallTile,
                               const __half* A, const __half* Bt, void* D,
                               int M, int N, int K, int lda, int ldB,
                               const float* bias, float alpha, float beta, int flags,
                               const float* addA = nullptr, const float* addC = nullptr,
                               const int* idxFlat = nullptr,
                               const __half* A2 = nullptr, const __half* Bt2 = nullptr,
                               void* D2 = nullptr, int splitK = 1)
{
    const int bm = smallTile ? 64 : 128;
    dim3 grid(M / bm, N / 128, splitK > 1 ? splitK : (A2 ? 2 : 1));
    if (smallTile)
        gemm_f16_kernel<2><<<grid, 256, GEMM_SMEM_BYTES>>>(A, Bt, D, M, N, K, lda, ldB,
                                                           bias, alpha, beta, flags,
                                                           addA, addC, idxFlat,
                                                           A2, Bt2, D2, splitK);
    else
        gemm_f16_kernel<4><<<grid, 256, GEMM_SMEM_BYTES>>>(A, Bt, D, M, N, K, lda, ldB,
                                                           bias, alpha, beta, flags,
                                                           addA, addC, idxFlat,
                                                           A2, Bt2, D2, splitK);
}

extern "C" void kernel_launch(void* const* d_in, const int* in_sizes, int n_in,
                              void* d_out, int out_size)
{
    (void)in_sizes; (void)n_in; (void)out_size;

    const float* node  = (const float*)d_in[0];
    const float* edges = (const float*)d_in[1];
    const int*   nidx  = (const int*)  d_in[2];
    const float* mask  = (const float*)d_in[3];
    const float* w0    = (const float*)d_in[4];
    const float* b0    = (const float*)d_in[5];
    const float* w1    = (const float*)d_in[6];
    const float* b1    = (const float*)d_in[7];
    const float* w2    = (const float*)d_in[8];
    const float* b2    = (const float*)d_in[9];
    const float* ln1w  = (const float*)d_in[10];
    const float* ln1b  = (const float*)d_in[11];
    const float* dw0   = (const float*)d_in[12];
    const float* db0   = (const float*)d_in[13];
    const float* dw1   = (const float*)d_in[14];
    const float* db1   = (const float*)d_in[15];
    const float* ln2w  = (const float*)d_in[16];
    const float* ln2b  = (const float*)d_in[17];

    __half *ET, *H1, *H2, *T, *Xt, *NT, *X1t, *Sb;
    __half *w0T, *w1T, *w2T, *dw0T, *dw1T;
    float *Ab, *Cb, *AGGP, *DP, *X, *X1;
    cudaGetSymbolAddress((void**)&ET,   g_ET);
    cudaGetSymbolAddress((void**)&H1,   g_H1);
    cudaGetSymbolAddress((void**)&H2,   g_H2);
    cudaGetSymbolAddress((void**)&T,    g_T);
    cudaGetSymbolAddress((void**)&Xt,   g_Xt);
    cudaGetSymbolAddress((void**)&NT,   g_NT);
    cudaGetSymbolAddress((void**)&X1t,  g_X1t);
    cudaGetSymbolAddress((void**)&Sb,   g_Sb);
    cudaGetSymbolAddress((void**)&Ab,   g_A);
    cudaGetSymbolAddress((void**)&Cb,   g_C);
    cudaGetSymbolAddress((void**)&AGGP, g_AGGP);
    cudaGetSymbolAddress((void**)&DP,   g_DP);
    cudaGetSymbolAddress((void**)&X,    g_X);
    cudaGetSymbolAddress((void**)&X1,   g_X1);
    cudaGetSymbolAddress((void**)&w0T,  g_w0T);
    cudaGetSymbolAddress((void**)&w1T,  g_w1T);
    cudaGetSymbolAddress((void**)&w2T,  g_w2T);
    cudaGetSymbolAddress((void**)&dw0T, g_dw0T);
    cudaGetSymbolAddress((void**)&dw1T, g_dw1T);

    cudaFuncSetAttribute(gemm_f16_kernel<4>,
                         cudaFuncAttributeMaxDynamicSharedMemorySize, GEMM_SMEM_BYTES);
    cudaFuncSetAttribute(gemm_f16_kernel<2>,
                         cudaFuncAttributeMaxDynamicSharedMemorySize, GEMM_SMEM_BYTES);

    // ---- preamble: 2 launches, so launch #3 is the big (c) GEMM for ncu ----
    prep_kernel<<<(int)((N4E + 255) / 256), 256>>>(edges, ET, node, X, Xt, NT);  // 0
    transpose_all_kernel<<<dim3(48, 48, 15), dim3(32, 8)>>>(
        w0, w1, w2, dw0, dw1, w0T, w1T, w2T, dw0T, dw1T);                        // 1

    for (int i = 0; i < LAYERS; i++) {
        const __half* w0L  = w0T  + (size_t)i * NF * MIN_;
        const float*  b0L  = b0   + (size_t)i * NF;
        const __half* w1L  = w1T  + (size_t)i * NF * NF;
        const float*  b1L  = b1   + (size_t)i * NF;
        const __half* w2L  = w2T  + (size_t)i * NF * NF;
        const float*  b2L  = b2   + (size_t)i * NF;
        const __half* dw0L = dw0T + (size_t)i * MIN_ * NF;
        const float*  db0L = db0  + (size_t)i * MIN_;
        const __half* dw1L = dw1T + (size_t)i * NF * MIN_;
        const float*  db1L = db1  + (size_t)i * NF;

        // (a)+(b) merged (small tile): Ab = x@W0a + b0 ; Cb = node@W0d   (launch 2)
        launch_gemm(true, Xt, w0L, Ab, NN, NF, NF, NF, MIN_, b0L, 1.f, 1.f, 0,
                    nullptr, nullptr, nullptr,
                    NT, w0L + 1152, Cb);
        // (c) H1 = fp16(gelu(edges @ W0b + A[m/48] + C[idx]))            (launch 3 <- ncu)
        launch_gemm(false, ET, w0L + 384, H1, NROWS, NF, NF, NF, MIN_,
                    nullptr, 1.f, 0.f, 1 | 4 | 8, Ab, Cb, nidx);
        // (d) H2 = fp16(gelu(H1 @ W1 + b1))
        launch_gemm(false, H1, w1L, H2, NROWS, NF, NF, NF, NF, b1L, 1.f, 1.f, 1 | 8);
        // (e) S = fp16(sum_k H2)
        reduce48_kernel<<<NN, NF>>>(H2, Sb);
        // (f) AGG parts = (S @ W2)/30 (+ (48/30) b2 in part 0), split-K=3 (small tile)
        launch_gemm(true, Sb, w2L, AGGP, NN, NF, NF, NF, NF, b2L,
                    1.f / 30.f, 48.f / 30.f, 0,
                    nullptr, nullptr, nullptr, nullptr, nullptr, nullptr, 3);
        // (g) x1 = LN(x + sum AGG parts)
        ln_kernel<<<NN, NF>>>(X, AGGP, AGGP + (size_t)NN * NF, AGGP + (size_t)2 * NN * NF,
                              ln1w + (size_t)i * NF, ln1b + (size_t)i * NF,
                              nullptr, X1, X1t);
        // (h) T = fp16(gelu(x1 @ dense_w0 + db0))
        launch_gemm(false, X1t, dw0L, T, NN, MIN_, NF, NF, NF, db0L, 1.f, 1.f, 1 | 8);
        // (i) D parts = T @ dense_w1 (+ db1 in part 0), split-K=3 (small tile)
        launch_gemm(true, T, dw1L, DP, NN, NF, MIN_, MIN_, MIN_, db1L, 1.f, 1.f, 0,
                    nullptr, nullptr, nullptr, nullptr, nullptr, nullptr, 3);
        // (j) x = mask * LN(x1 + sum D parts)
        float*  xout  = (i == LAYERS - 1) ? (float*)d_out : X;
        __half* xout2 = (i == LAYERS - 1) ? nullptr : Xt;
        ln_kernel<<<NN, NF>>>(X1, DP, DP + (size_t)NN * NF, DP + (size_t)2 * NN * NF,
                              ln2w + (size_t)i * NF, ln2b + (size_t)i * NF,
                              mask, xout, xout2);
    }
}

// round 12
// speedup vs baseline: 2.1568x; 1.0996x over previous
#include <cuda_runtime.h>
#include <cuda_fp16.h>
#include <cstdint>
#include <cstddef>

// ---------------- problem constants ----------------
#define NN    2048
#define KNB   48
#define NF    384
#define MIN_  1536
#define NROWS (NN*KNB)        // 98304
#define LAYERS 3

// ---------------- device scratch ----------------
__device__ __half g_ET[(size_t)NROWS * NF];
__device__ __half g_H1[(size_t)NROWS * NF];
__device__ __half g_H2[(size_t)NROWS * NF];
__device__ __half g_T [NN * MIN_];
__device__ __half g_Xt [NN * NF];
__device__ __half g_NT [NN * NF];
__device__ __half g_X1t[NN * NF];
__device__ __half g_Sb [NN * NF];
__device__ float  g_A  [NN * NF];
__device__ float  g_C  [NN * NF];
__device__ float  g_AGGP[3 * NN * NF];
__device__ float  g_DP  [3 * NN * NF];
__device__ float  g_X  [NN * NF];
__device__ float  g_X1 [NN * NF];
// transposed fp16 weights, [N][K] row-major (k-contiguous)
__device__ __half g_w0T [LAYERS * NF * MIN_];
__device__ __half g_w1T [LAYERS * NF * NF];
__device__ __half g_w2T [LAYERS * NF * NF];
__device__ __half g_dw0T[LAYERS * MIN_ * NF];
__device__ __half g_dw1T[LAYERS * NF * MIN_];

// ---------------- helpers ----------------
__device__ __forceinline__ float gelu_exact(float x) {
    return 0.5f * x * (1.0f + erff(x * 0.70710678118654752440f));
}

__device__ __forceinline__ void mma_f16(float* c, const uint32_t* a, const uint32_t* b) {
    asm volatile(
        "mma.sync.aligned.m16n8k16.row.col.f32.f16.f16.f32 "
        "{%0,%1,%2,%3}, {%4,%5,%6,%7}, {%8,%9}, {%0,%1,%2,%3};\n"
        : "+f"(c[0]), "+f"(c[1]), "+f"(c[2]), "+f"(c[3])
        : "r"(a[0]), "r"(a[1]), "r"(a[2]), "r"(a[3]),
          "r"(b[0]), "r"(b[1]));
}

#define LDSM_X4(r0, r1, r2, r3, addr) \
    asm volatile("ldmatrix.sync.aligned.m8n8.x4.shared.b16 {%0,%1,%2,%3}, [%4];" \
                 : "=r"(r0), "=r"(r1), "=r"(r2), "=r"(r3) : "r"(addr))

__device__ __forceinline__ void cp_async16(void* smem_dst, const void* gmem_src) {
    uint32_t s = (uint32_t)__cvta_generic_to_shared(smem_dst);
    asm volatile("cp.async.cg.shared.global [%0], [%1], 16;\n" :: "r"(s), "l"(gmem_src));
}
#define CP_COMMIT()  asm volatile("cp.async.commit_group;\n" ::: "memory")
#define CP_WAIT(n)   asm volatile("cp.async.wait_group %0;\n" :: "n"(n) : "memory")

// ============================================================
// FP16-input GEMM (fp32 acc), ldmatrix fragments, BK=64 / 3-stage cp.async,
// ONE __syncthreads per 64-wide K-iter, 2 CTAs/SM.
// Template NWM = warps along M (4 -> BM=128, 2 -> BM=64). BN=128 fixed.
//   D[M,N] = epi( A[M,K] @ Bt[N,K]^T ), A stride lda, Bt stride ldB.
// flags: 1=gelu, 4=gather(addA[m/48]+addC[idx[m]]), 8=output fp16
// splitK>1: blockIdx.z = part p (fp32 parts at D + p*M*N, bias part0 only)
// splitK==1 && blockIdx.z==1: second problem (A2,Bt2,D2), no bias.
// ============================================================
#define BK 64
#define SROWB 144                     // bytes/row: 128B data + 16B pad (9 coprime 8)
#define STAGE_B (128*SROWB)           // 18432 B
#define NSTAGE 3
#define GEMM_SMEM_BYTES (2*NSTAGE*STAGE_B)   // 110592 B; x2 CTAs = 216KB

template<int NWM>
__global__ __launch_bounds__(256, 2) void gemm_f16_kernel(
    const __half* __restrict__ A, const __half* __restrict__ Bt,
    void* __restrict__ Dv, int M, int N, int K, int lda, int ldB,
    const float* __restrict__ bias, float alpha, float beta, int flags,
    const float* __restrict__ addA, const float* __restrict__ addC,
    const int* __restrict__ idxFlat,
    const __half* __restrict__ A2, const __half* __restrict__ Bt2,
    void* __restrict__ D2, int splitK)
{
    constexpr int BM_   = NWM * 32;
    constexpr int NWN   = 8 / NWM;
    constexpr int NCOLS = 128 / NWN;      // per-warp n columns
    constexpr int NI    = NCOLS / 8;      // 8 or 4

    if (splitK > 1) {
        const int part = blockIdx.z;
        const int Kp = K / splitK;
        A  += (size_t)part * Kp;
        Bt += (size_t)part * Kp;
        Dv = (void*)((float*)Dv + (size_t)part * M * N);
        if (part) bias = nullptr;
        K = Kp;
    } else if (blockIdx.z == 1) {
        A = A2; Bt = Bt2; Dv = D2; bias = nullptr;
    }

    extern __shared__ char smc[];   // [A x NSTAGE][B x NSTAGE]
    const uint32_t sbase = (uint32_t)__cvta_generic_to_shared(smc);

    const int tid  = threadIdx.x;
    const int m0   = blockIdx.x * BM_;
    const int n0   = blockIdx.y * 128;
    const int warp = tid >> 5;
    const int lane = tid & 31;
    const int wm   = warp / NWN;
    const int wn   = warp % NWN;
    const int gid  = lane >> 2;
    const int tig  = lane & 3;

    float acc[2][NI][4];
    #pragma unroll
    for (int a = 0; a < 2; a++)
        #pragma unroll
        for (int b = 0; b < NI; b++)
            #pragma unroll
            for (int c = 0; c < 4; c++) acc[a][b][c] = 0.f;

    // ldmatrix fragment base addresses (bytes, stage 0)
    const uint32_t aFrag = sbase +
        (uint32_t)((wm * 32 + (lane & 15)) * SROWB + (lane >> 4) * 16);
    const uint32_t bFrag = sbase + (uint32_t)(NSTAGE * STAGE_B) +
        (uint32_t)(((wn * NCOLS + ((lane >> 4) * 8) + (lane & 7)) * SROWB) +
                   (((lane >> 3) & 1) * 16));

    const __half* Abase = A  + (size_t)m0 * lda;
    const __half* Bbase = Bt + (size_t)n0 * ldB;
    const int KT = K / BK;

    auto produce = [&](int kt, int buf) {
        const __half* Ap = Abase + kt * BK;
        char* As = smc + buf * STAGE_B;
        #pragma unroll
        for (int i = 0; i < BM_ * 8 / 256; i++) {
            int lin = tid + i * 256;
            int row = lin >> 3, ch = lin & 7;       // 8 x 16B chunks per 128B row
            cp_async16(As + row * SROWB + ch * 16, Ap + (size_t)row * lda + ch * 8);
        }
        const __half* Bp = Bbase + kt * BK;
        char* Bs = smc + (NSTAGE + buf) * STAGE_B;
        #pragma unroll
        for (int i = 0; i < 4; i++) {
            int lin = tid + i * 256;
            int row = lin >> 3, ch = lin & 7;
            cp_async16(Bs + row * SROWB + ch * 16, Bp + (size_t)row * ldB + ch * 8);
        }
        CP_COMMIT();
    };

    // prologue: 2 stages ahead
    produce(0, 0);
    if (KT > 1) produce(1, 1);

    for (int kt = 0; kt < KT; kt++) {
        const int cur = kt % NSTAGE;
        if (kt + 1 < KT) { CP_WAIT(1); }
        else             { CP_WAIT(0); }
        __syncthreads();

        const uint32_t so = (uint32_t)(cur * STAGE_B);
        #pragma unroll
        for (int j = 0; j < 4; j++) {         // four k16 steps per BK=64
            const uint32_t aA = aFrag + so + j * 32;
            const uint32_t bA = bFrag + so + j * 32;
            uint32_t a0[4], a1[4], bf[NI][2];
            LDSM_X4(a0[0], a0[1], a0[2], a0[3], aA);
            LDSM_X4(a1[0], a1[1], a1[2], a1[3], aA + 16 * SROWB);
            #pragma unroll
            for (int gg = 0; gg < NI / 2; gg++)
                LDSM_X4(bf[2*gg][0], bf[2*gg][1], bf[2*gg+1][0], bf[2*gg+1][1],
                        bA + (uint32_t)(gg * 16 * SROWB));
            #pragma unroll
            for (int ni = 0; ni < NI; ni++) {
                mma_f16(acc[0][ni], a0, bf[ni]);
                mma_f16(acc[1][ni], a1, bf[ni]);
            }
        }
        // produce AFTER barrier: stage (kt+2)%3 == (kt-1)%3, whose readers
        // all finished before this iteration's __syncthreads.
        if (kt + 2 < KT) produce(kt + 2, (kt + 2) % NSTAGE);
    }

    // ---- epilogue ----
    const int doGelu = flags & 1;
    const int doGath = flags & 4;
    const int outHalf = flags & 8;
    #pragma unroll
    for (int mi = 0; mi < 2; mi++) {
        #pragma unroll
        for (int h = 0; h < 2; h++) {
            const int m = m0 + wm * 32 + mi * 16 + h * 8 + gid;
            const float* aArow = nullptr;
            const float* aCrow = nullptr;
            if (doGath) {
                aArow = addA + (size_t)(m / KNB) * N;
                aCrow = addC + (size_t)idxFlat[m] * N;
            }
            #pragma unroll
            for (int ni = 0; ni < NI; ni++) {
                const int n = n0 + wn * NCOLS + ni * 8 + tig * 2;
                float v0 = acc[mi][ni][h * 2 + 0] * alpha;
                float v1 = acc[mi][ni][h * 2 + 1] * alpha;
                if (bias) { v0 += beta * bias[n]; v1 += beta * bias[n + 1]; }
                if (doGath) {
                    v0 += aArow[n] + aCrow[n];
                    v1 += aArow[n + 1] + aCrow[n + 1];
                }
                if (doGelu) { v0 = gelu_exact(v0); v1 = gelu_exact(v1); }
                if (outHalf) {
                    __half2* Drow = (__half2*)((__half*)Dv + (size_t)m * N + n);
                    *Drow = __floats2half2_rn(v0, v1);
                } else {
                    float2* Drow = (float2*)((float*)Dv + (size_t)m * N + n);
                    *Drow = make_float2(v0, v1);
                }
            }
        }
    }
}

// ---------------- supporting kernels ----------------
__global__ void reduce48_kernel(const __half* __restrict__ H2, __half* __restrict__ S) {
    int i = blockIdx.x;
    int n = threadIdx.x;
    const __half* p = H2 + (size_t)i * KNB * NF + n;
    float s = 0.f;
    #pragma unroll
    for (int k = 0; k < KNB; k++) s += __half2float(p[(size_t)k * NF]);
    S[(size_t)i * NF + n] = __float2half(s);
}

// layernorm of (a + p0 [+ p1] [+ p2]); out (fp32), out2 (fp16, optional); mask optional
__global__ void ln_kernel(const float* __restrict__ a,
                          const float* __restrict__ p0,
                          const float* __restrict__ p1,
                          const float* __restrict__ p2,
                          const float* __restrict__ w, const float* __restrict__ bv,
                          const float* __restrict__ mask,
                          float* __restrict__ out, __half* __restrict__ out2)
{
    int i = blockIdx.x;
    int n = threadIdx.x;
    size_t o = (size_t)i * NF + n;
    float v = a[o] + p0[o];
    if (p1) v += p1[o];
    if (p2) v += p2[o];

    __shared__ float s1[12], s2[12];
    float x1 = v, x2 = v * v;
    #pragma unroll
    for (int off = 16; off; off >>= 1) {
        x1 += __shfl_down_sync(0xFFFFFFFFu, x1, off);
        x2 += __shfl_down_sync(0xFFFFFFFFu, x2, off);
    }
    int wi = n >> 5, li = n & 31;
    if (li == 0) { s1[wi] = x1; s2[wi] = x2; }
    __syncthreads();
    __shared__ float mean_s, rstd_s;
    if (n == 0) {
        float t1 = 0.f, t2 = 0.f;
        #pragma unroll
        for (int j = 0; j < 12; j++) { t1 += s1[j]; t2 += s2[j]; }
        float mu  = t1 * (1.f / NF);
        float var = t2 * (1.f / NF) - mu * mu;
        mean_s = mu;
        rstd_s = rsqrtf(var + 1e-5f);
    }
    __syncthreads();
    float rr = (v - mean_s) * rstd_s * w[n] + bv[n];
    if (mask) rr *= mask[i];
    out[o] = rr;
    if (out2) out2[o] = __float2half(rr);
}

// merged preamble: edges fp32->fp16 AND node -> X(fp32), Xt(fp16), NT(fp16)
#define N4E ((size_t)NROWS * NF / 4)
#define N4N (NN * NF / 4)
__global__ void prep_kernel(const float* __restrict__ edges, __half* __restrict__ ET,
                            const float* __restrict__ node, float* __restrict__ X,
                            __half* __restrict__ Xt, __half* __restrict__ NT)
{
    size_t i = (size_t)blockIdx.x * blockDim.x + threadIdx.x;
    if (i < N4E) {
        float4 v = reinterpret_cast<const float4*>(edges)[i];
        __half2* d = reinterpret_cast<__half2*>(ET + i * 4);
        d[0] = __floats2half2_rn(v.x, v.y);
        d[1] = __floats2half2_rn(v.z, v.w);
    }
    if (i < N4N) {
        float4 v = reinterpret_cast<const float4*>(node)[i];
        reinterpret_cast<float4*>(X)[i] = v;
        __half2 h0 = __floats2half2_rn(v.x, v.y);
        __half2 h1 = __floats2half2_rn(v.z, v.w);
        __half2* xt = reinterpret_cast<__half2*>(Xt + i * 4);
        __half2* nt = reinterpret_cast<__half2*>(NT + i * 4);
        xt[0] = h0; xt[1] = h1;
        nt[0] = h0; nt[1] = h1;
    }
}

// all weight transposes (fp32 [K,N] -> fp16 [N,K]) in one launch; z = type*3 + layer
__global__ void transpose_all_kernel(
    const float* __restrict__ w0,  const float* __restrict__ w1,
    const float* __restrict__ w2,  const float* __restrict__ dw0,
    const float* __restrict__ dw1,
    __half* __restrict__ w0T,  __half* __restrict__ w1T,
    __half* __restrict__ w2T,  __half* __restrict__ dw0T,
    __half* __restrict__ dw1T)
{
    const int z = blockIdx.z;
    const int type = z / 3, layer = z % 3;
    const float* in; __half* out; int K, N;
    switch (type) {
        case 0: in = w0  + (size_t)layer*MIN_*NF; out = w0T  + (size_t)layer*NF*MIN_; K = MIN_; N = NF;   break;
        case 1: in = w1  + (size_t)layer*NF*NF;   out = w1T  + (size_t)layer*NF*NF;   K = NF;   N = NF;   break;
        case 2: in = w2  + (size_t)layer*NF*NF;   out = w2T  + (size_t)layer*NF*NF;   K = NF;   N = NF;   break;
        case 3: in = dw0 + (size_t)layer*NF*MIN_; out = dw0T + (size_t)layer*MIN_*NF; K = NF;   N = MIN_; break;
        default:in = dw1 + (size_t)layer*MIN_*NF; out = dw1T + (size_t)layer*NF*MIN_; K = MIN_; N = NF;   break;
    }
    const int k0 = blockIdx.x * 32, n0 = blockIdx.y * 32;
    if (k0 >= K || n0 >= N) return;

    __shared__ float t[32][33];
    const int x = threadIdx.x, y = threadIdx.y;
    #pragma unroll
    for (int i = y; i < 32; i += 8)
        t[i][x] = in[(size_t)(k0 + i) * N + n0 + x];
    __syncthreads();
    #pragma unroll
    for (int i = y; i < 32; i += 8)
        out[(size_t)(n0 + i) * K + k0 + x] = __float2half(t[x][i]);
}

// ---------------- host orchestration ----------------
static inline void launch_gemm(bool smallTile,
                               const __half* A, const __half* Bt, void* D,
                               int M, int N, int K, int lda, int ldB,
                               const float* bias, float alpha, float beta, int flags,
                               const float* addA = nullptr, const float* addC = nullptr,
                               const int* idxFlat = nullptr,
                               const __half* A2 = nullptr, const __half* Bt2 = nullptr,
                               void* D2 = nullptr, int splitK = 1)
{
    const int bm = smallTile ? 64 : 128;
    dim3 grid(M / bm, N / 128, splitK > 1 ? splitK : (A2 ? 2 : 1));
    if (smallTile)
        gemm_f16_kernel<2><<<grid, 256, GEMM_SMEM_BYTES>>>(A, Bt, D, M, N, K, lda, ldB,
                                                           bias, alpha, beta, flags,
                                                           addA, addC, idxFlat,
                                                           A2, Bt2, D2, splitK);
    else
        gemm_f16_kernel<4><<<grid, 256, GEMM_SMEM_BYTES>>>(A, Bt, D, M, N, K, lda, ldB,
                                                           bias, alpha, beta, flags,
                                                           addA, addC, idxFlat,
                                                           A2, Bt2, D2, splitK);
}

extern "C" void kernel_launch(void* const* d_in, const int* in_sizes, int n_in,
                              void* d_out, int out_size)
{
    (void)in_sizes; (void)n_in; (void)out_size;

    const float* node  = (const float*)d_in[0];
    const float* edges = (const float*)d_in[1];
    const int*   nidx  = (const int*)  d_in[2];
    const float* mask  = (const float*)d_in[3];
    const float* w0    = (const float*)d_in[4];
    const float* b0    = (const float*)d_in[5];
    const float* w1    = (const float*)d_in[6];
    const float* b1    = (const float*)d_in[7];
    const float* w2    = (const float*)d_in[8];
    const float* b2    = (const float*)d_in[9];
    const float* ln1w  = (const float*)d_in[10];
    const float* ln1b  = (const float*)d_in[11];
    const float* dw0   = (const float*)d_in[12];
    const float* db0   = (const float*)d_in[13];
    const float* dw1   = (const float*)d_in[14];
    const float* db1   = (const float*)d_in[15];
    const float* ln2w  = (const float*)d_in[16];
    const float* ln2b  = (const float*)d_in[17];

    __half *ET, *H1, *H2, *T, *Xt, *NT, *X1t, *Sb;
    __half *w0T, *w1T, *w2T, *dw0T, *dw1T;
    float *Ab, *Cb, *AGGP, *DP, *X, *X1;
    cudaGetSymbolAddress((void**)&ET,   g_ET);
    cudaGetSymbolAddress((void**)&H1,   g_H1);
    cudaGetSymbolAddress((void**)&H2,   g_H2);
    cudaGetSymbolAddress((void**)&T,    g_T);
    cudaGetSymbolAddress((void**)&Xt,   g_Xt);
    cudaGetSymbolAddress((void**)&NT,   g_NT);
    cudaGetSymbolAddress((void**)&X1t,  g_X1t);
    cudaGetSymbolAddress((void**)&Sb,   g_Sb);
    cudaGetSymbolAddress((void**)&Ab,   g_A);
    cudaGetSymbolAddress((void**)&Cb,   g_C);
    cudaGetSymbolAddress((void**)&AGGP, g_AGGP);
    cudaGetSymbolAddress((void**)&DP,   g_DP);
    cudaGetSymbolAddress((void**)&X,    g_X);
    cudaGetSymbolAddress((void**)&X1,   g_X1);
    cudaGetSymbolAddress((void**)&w0T,  g_w0T);
    cudaGetSymbolAddress((void**)&w1T,  g_w1T);
    cudaGetSymbolAddress((void**)&w2T,  g_w2T);
    cudaGetSymbolAddress((void**)&dw0T, g_dw0T);
    cudaGetSymbolAddress((void**)&dw1T, g_dw1T);

    cudaFuncSetAttribute(gemm_f16_kernel<4>,
                         cudaFuncAttributeMaxDynamicSharedMemorySize, GEMM_SMEM_BYTES);
    cudaFuncSetAttribute(gemm_f16_kernel<2>,
                         cudaFuncAttributeMaxDynamicSharedMemorySize, GEMM_SMEM_BYTES);

    // ---- preamble: 2 launches, so launch #3 is the big (c) GEMM for ncu ----
    prep_kernel<<<(int)((N4E + 255) / 256), 256>>>(edges, ET, node, X, Xt, NT);  // 0
    transpose_all_kernel<<<dim3(48, 48, 15), dim3(32, 8)>>>(
        w0, w1, w2, dw0, dw1, w0T, w1T, w2T, dw0T, dw1T);                        // 1

    for (int i = 0; i < LAYERS; i++) {
        const __half* w0L  = w0T  + (size_t)i * NF * MIN_;
        const float*  b0L  = b0   + (size_t)i * NF;
        const __half* w1L  = w1T  + (size_t)i * NF * NF;
        const float*  b1L  = b1   + (size_t)i * NF;
        const __half* w2L  = w2T  + (size_t)i * NF * NF;
        const float*  b2L  = b2   + (size_t)i * NF;
        const __half* dw0L = dw0T + (size_t)i * MIN_ * NF;
        const float*  db0L = db0  + (size_t)i * MIN_;
        const __half* dw1L = dw1T + (size_t)i * NF * MIN_;
        const float*  db1L = db1  + (size_t)i * NF;

        // (a)+(b) merged (small tile): Ab = x@W0a + b0 ; Cb = node@W0d   (launch 2)
        launch_gemm(true, Xt, w0L, Ab, NN, NF, NF, NF, MIN_, b0L, 1.f, 1.f, 0,
                    nullptr, nullptr, nullptr,
                    NT, w0L + 1152, Cb);
        // (c) H1 = fp16(gelu(edges @ W0b + A[m/48] + C[idx]))            (launch 3 <- ncu)
        launch_gemm(false, ET, w0L + 384, H1, NROWS, NF, NF, NF, MIN_,
                    nullptr, 1.f, 0.f, 1 | 4 | 8, Ab, Cb, nidx);
        // (d) H2 = fp16(gelu(H1 @ W1 + b1))
        launch_gemm(false, H1, w1L, H2, NROWS, NF, NF, NF, NF, b1L, 1.f, 1.f, 1 | 8);
        // (e) S = fp16(sum_k H2)
        reduce48_kernel<<<NN, NF>>>(H2, Sb);
        // (f) AGG parts = (S @ W2)/30 (+ (48/30) b2 in part 0), split-K=3 (small tile)
        launch_gemm(true, Sb, w2L, AGGP, NN, NF, NF, NF, NF, b2L,
                    1.f / 30.f, 48.f / 30.f, 0,
                    nullptr, nullptr, nullptr, nullptr, nullptr, nullptr, 3);
        // (g) x1 = LN(x + sum AGG parts)
        ln_kernel<<<NN, NF>>>(X, AGGP, AGGP + (size_t)NN * NF, AGGP + (size_t)2 * NN * NF,
                              ln1w + (size_t)i * NF, ln1b + (size_t)i * NF,
                              nullptr, X1, X1t);
        // (h) T = fp16(gelu(x1 @ dense_w0 + db0))
        launch_gemm(false, X1t, dw0L, T, NN, MIN_, NF, NF, NF, db0L, 1.f, 1.f, 1 | 8);
        // (i) D parts = T @ dense_w1 (+ db1 in part 0), split-K=3 (small tile)
        launch_gemm(true, T, dw1L, DP, NN, NF, MIN_, MIN_, MIN_, db1L, 1.f, 1.f, 0,
                    nullptr, nullptr, nullptr, nullptr, nullptr, nullptr, 3);
        // (j) x = mask * LN(x1 + sum D parts)
        float*  xout  = (i == LAYERS - 1) ? (float*)d_out : X;
        __half* xout2 = (i == LAYERS - 1) ? nullptr : Xt;
        ln_kernel<<<NN, NF>>>(X1, DP, DP + (size_t)NN * NF, DP + (size_t)2 * NN * NF,
                              ln2w + (size_t)i * NF, ln2b + (size_t)i * NF,
                              mask, xout, xout2);
    }
}